// round 6
// baseline (speedup 1.0000x reference)
#include <cuda_runtime.h>
#include <cuda_bf16.h>
#include <cstdint>

#define BB 512
#define HH 1024
#define OO 1024
#define SS 64
#define TT 128

// ---------------------------------------------------------------------------
// Device-global scratch (allocation-free)
// ---------------------------------------------------------------------------
__device__ __align__(256) __nv_bfloat16 g_Wih_hi[3072 * 1024], g_Wih_lo[3072 * 1024];
__device__ __align__(256) __nv_bfloat16 g_Whh_hi[3072 * 1024], g_Whh_lo[3072 * 1024];
__device__ __align__(256) __nv_bfloat16 g_Wo_hi[1024 * 1024], g_Wo_lo[1024 * 1024];
__device__ __align__(256) __nv_bfloat16 g_WoT_hi[1024 * 1024], g_WoT_lo[1024 * 1024];
__device__ __align__(256) __nv_bfloat16 g_Wc1_hi[1024 * 1024], g_Wc1_lo[1024 * 1024];
__device__ __align__(256) __nv_bfloat16 g_WcB_hi[1024 * 1024], g_WcB_lo[1024 * 1024];
__device__ __align__(256) __nv_bfloat16 g_WcF_hi[1024 * 1024], g_WcF_lo[1024 * 1024];
__device__ __align__(256) float g_WaF[64 * 1024];
__device__ __align__(256) float g_baF[64];
__device__ __align__(256) float g_bcF[1024];
__device__ __align__(256) __nv_bfloat16 g_enc_hi[(size_t)32768 * 1024];
__device__ __align__(256) __nv_bfloat16 g_enc_lo[(size_t)32768 * 1024];
__device__ __align__(256) float g_encW[(size_t)32768 * 1024];   // enc @ Wc2^T
__device__ __align__(256) float g_P[512 * 1024];
__device__ __align__(256) float g_U[512 * 1024];
__device__ __align__(256) __nv_bfloat16 g_gr_hi[512 * 1024], g_gr_lo[512 * 1024];
__device__ __align__(256) float g_h[512 * 1024];
__device__ __align__(256) __nv_bfloat16 g_hhi[512 * 1024], g_hlo[512 * 1024];
__device__ __align__(256) float g_gi[512 * 3072], g_gh[512 * 3072];
__device__ __align__(256) __nv_bfloat16 g_Hall_hi[(size_t)512 * 128 * 1024];
__device__ __align__(256) __nv_bfloat16 g_Hall_lo[(size_t)512 * 128 * 1024];
__device__ __align__(256) float g_zero[4096];

// ---------------------------------------------------------------------------
// Helpers
// ---------------------------------------------------------------------------
__device__ __forceinline__ void split2(float v, __nv_bfloat16& hi, __nv_bfloat16& lo) {
    hi = __float2bfloat16(v);
    lo = __float2bfloat16(v - __bfloat162float(hi));
}

__device__ __forceinline__ uint32_t smem_u32(const void* p) {
    uint32_t a;
    asm("{ .reg .u64 t; cvta.to.shared.u64 t, %1; cvt.u32.u64 %0, t; }" : "=r"(a) : "l"(p));
    return a;
}

__device__ __forceinline__ void ldsm_x4(uint32_t* r, uint32_t addr) {
    asm volatile("ldmatrix.sync.aligned.m8n8.x4.shared.b16 {%0,%1,%2,%3}, [%4];\n"
                 : "=r"(r[0]), "=r"(r[1]), "=r"(r[2]), "=r"(r[3]) : "r"(addr));
}

__device__ __forceinline__ void mma_bf16(float* c, const uint32_t* a, const uint32_t* b) {
    asm volatile(
        "mma.sync.aligned.m16n8k16.row.col.f32.bf16.bf16.f32 "
        "{%0,%1,%2,%3}, {%4,%5,%6,%7}, {%8,%9}, {%0,%1,%2,%3};\n"
        : "+f"(c[0]), "+f"(c[1]), "+f"(c[2]), "+f"(c[3])
        : "r"(a[0]), "r"(a[1]), "r"(a[2]), "r"(a[3]), "r"(b[0]), "r"(b[1]));
}

__device__ __forceinline__ void cp16a(uint32_t dst, const void* src) {
    asm volatile("cp.async.cg.shared.global [%0], [%1], 16;\n" :: "r"(dst), "l"(src));
}
#define CP_COMMIT() asm volatile("cp.async.commit_group;\n" ::: "memory")
#define CP_WAIT1()  asm volatile("cp.async.wait_group 1;\n" ::: "memory")

// ---------------------------------------------------------------------------
// Engine v3: fused 3-pass split-bf16 GEMM block.
// C[M,N] = A@W^T + bias via Ahi@Whi + Ahi@Wlo + Alo@Whi, fp32 accum.
// Tile 64(M) x 128(N), BK=64, 256 threads (8 warps 2x4, warp tile 32x32).
// Row stride 72 elems (144B) -> 16B-aligned cp.async, conflict-free ldmatrix.
// smem: 2 stages x 55296 B = 110592 B dynamic.
// mode 0: fp32 out; 1: relu -> split bf16; 2: split bf16 (no relu).
// ---------------------------------------------------------------------------
struct GProb {
    const __nv_bfloat16 *Ahi, *Alo; int lda;
    const __nv_bfloat16 *Whi, *Wlo; int ldw;
    int K;
    const float* bias;
    float* Cf; int ldc;
    __nv_bfloat16 *Chi, *Clo; int ldch;
    int mode;
};
struct GP2 { GProb p[2]; };

#define ENG_ALO 9216u
#define ENG_WHI 18432u
#define ENG_WLO 36864u
#define ENG_STAGE 55296u
#define ENG_SMEM 110592

__device__ __forceinline__ void gemm_block(const GProb& p, int bx, int by, uint32_t smbase)
{
    const int tid = threadIdx.x, warp = tid >> 5, lane = tid & 31;
    const int m0 = by * 64, n0 = bx * 128;
    const int S = p.K >> 6;
    const int wm = warp >> 2, wn = warp & 3;
    const int lr = tid >> 1;              // 0..127 loader row
    const int lc = (tid & 1) * 4;         // chunk base (x16B)

    float acc[2][4][4];
#pragma unroll
    for (int mi = 0; mi < 2; ++mi)
#pragma unroll
        for (int nf = 0; nf < 4; ++nf)
#pragma unroll
            for (int q = 0; q < 4; ++q) acc[mi][nf][q] = 0.f;

    const __nv_bfloat16* abase = (lr < 64)
        ? p.Ahi + (size_t)(m0 + lr) * p.lda
        : p.Alo + (size_t)(m0 + lr - 64) * p.lda;
    const __nv_bfloat16* w1base = p.Whi + (size_t)(n0 + lr) * p.ldw;
    const __nv_bfloat16* w2base = p.Wlo + (size_t)(n0 + lr) * p.ldw;
    const uint32_t rowb = (uint32_t)lr * 144 + (uint32_t)lc * 16;

    auto load_stage = [&](int s) {
        const int k0 = (s << 6) + lc * 8;
        const uint32_t sb = smbase + (uint32_t)(s & 1) * ENG_STAGE;
#pragma unroll
        for (int c = 0; c < 4; ++c)
            cp16a(sb + rowb + c * 16, abase + k0 + c * 8);
#pragma unroll
        for (int c = 0; c < 4; ++c)
            cp16a(sb + ENG_WHI + rowb + c * 16, w1base + k0 + c * 8);
#pragma unroll
        for (int c = 0; c < 4; ++c)
            cp16a(sb + ENG_WLO + rowb + c * 16, w2base + k0 + c * 8);
    };

    load_stage(0); CP_COMMIT();
    load_stage(1); CP_COMMIT();

    const int arow = wm * 32 + (lane & 15);
    const int acolb = (lane >> 4) << 3;
    const int g = lane >> 3;
    const int brow = wn * 32 + ((g >> 1) << 3) + (lane & 7);
    const int bcolb = (g & 1) << 3;

    for (int s = 0; s < S; ++s) {
        CP_WAIT1();
        __syncthreads();
        const uint32_t sb = smbase + (uint32_t)(s & 1) * ENG_STAGE;
#pragma unroll
        for (int kk = 0; kk < 4; ++kk) {
            const int acol = kk * 16 + acolb;
            uint32_t ahi[2][4], alo[2][4];
#pragma unroll
            for (int mi = 0; mi < 2; ++mi) {
                const uint32_t off = (uint32_t)((arow + mi * 16) * 144 + acol * 2);
                ldsm_x4(ahi[mi], sb + off);
                ldsm_x4(alo[mi], sb + ENG_ALO + off);
            }
            const int bcol = kk * 16 + bcolb;
            uint32_t bhi[4][2], blo[4][2];
#pragma unroll
            for (int nh = 0; nh < 2; ++nh) {
                uint32_t r[4];
                const uint32_t off = (uint32_t)((brow + nh * 16) * 144 + bcol * 2);
                ldsm_x4(r, sb + ENG_WHI + off);
                bhi[nh * 2 + 0][0] = r[0]; bhi[nh * 2 + 0][1] = r[1];
                bhi[nh * 2 + 1][0] = r[2]; bhi[nh * 2 + 1][1] = r[3];
                ldsm_x4(r, sb + ENG_WLO + off);
                blo[nh * 2 + 0][0] = r[0]; blo[nh * 2 + 0][1] = r[1];
                blo[nh * 2 + 1][0] = r[2]; blo[nh * 2 + 1][1] = r[3];
            }
#pragma unroll
            for (int mi = 0; mi < 2; ++mi)
#pragma unroll
                for (int nf = 0; nf < 4; ++nf)
                    mma_bf16(acc[mi][nf], ahi[mi], bhi[nf]);
#pragma unroll
            for (int mi = 0; mi < 2; ++mi)
#pragma unroll
                for (int nf = 0; nf < 4; ++nf)
                    mma_bf16(acc[mi][nf], ahi[mi], blo[nf]);
#pragma unroll
            for (int mi = 0; mi < 2; ++mi)
#pragma unroll
                for (int nf = 0; nf < 4; ++nf)
                    mma_bf16(acc[mi][nf], alo[mi], bhi[nf]);
        }
        __syncthreads();
        if (s + 2 < S) load_stage(s + 2);
        CP_COMMIT();
    }

    const int row0 = m0 + wm * 32 + (lane >> 2);
    const int col0 = (bx * 128) + wn * 32 + ((lane & 3) << 1);
#pragma unroll
    for (int mi = 0; mi < 2; ++mi) {
#pragma unroll
        for (int nf = 0; nf < 4; ++nf) {
            const int col = col0 + nf * 8;
            const float b0 = p.bias[col], b1 = p.bias[col + 1];
#pragma unroll
            for (int half = 0; half < 2; ++half) {
                const int row = row0 + mi * 16 + half * 8;
                float v0 = acc[mi][nf][half * 2 + 0] + b0;
                float v1 = acc[mi][nf][half * 2 + 1] + b1;
                if (p.mode == 0) {
                    *(float2*)&p.Cf[(size_t)row * p.ldc + col] = make_float2(v0, v1);
                } else {
                    if (p.mode == 1) { v0 = fmaxf(v0, 0.f); v1 = fmaxf(v1, 0.f); }
                    __nv_bfloat162 hv, lv;
                    split2(v0, hv.x, lv.x); split2(v1, hv.y, lv.y);
                    *(__nv_bfloat162*)&p.Chi[(size_t)row * p.ldch + col] = hv;
                    *(__nv_bfloat162*)&p.Clo[(size_t)row * p.ldch + col] = lv;
                }
            }
        }
    }
}

__global__ __launch_bounds__(256, 2) void gemm_std_kernel(GP2 P)
{
    extern __shared__ char sm[];
    gemm_block(P.p[blockIdx.z], blockIdx.x, blockIdx.y, smem_u32(sm));
}

// ---------------------------------------------------------------------------
// K1: gh GEMM (192 blk) + U GEMM (64 blk) + attention->P (256 blk), one launch
// ---------------------------------------------------------------------------
struct K1Args {
    GProb gh, U;
    const float *h, *encW, *W, *bias;   // W: logits weight [64, wld]
    int wld;
    float* P;
};

__global__ __launch_bounds__(256, 2) void step1_kernel(K1Args a)
{
    extern __shared__ char sm[];
    const int bid = blockIdx.x;
    if (bid < 192) { gemm_block(a.gh, bid % 24, bid / 24, smem_u32(sm)); return; }
    if (bid < 256) { const int i = bid - 192; gemm_block(a.U, i & 7, i >> 3, smem_u32(sm)); return; }

    // ---- attention block: 2 batch rows ----
    float* sh   = (float*)sm;          // 2 x 1024
    float* slog = sh + 2048;           // 2 x 64
    float* sw   = slog + 128;          // 2 x 64
    const int tid = threadIdx.x;
    const int b0 = (bid - 256) * 2;

    for (int i = tid; i < 2048; i += 256)
        sh[i] = a.h[(size_t)b0 * 1024 + i];
    __syncthreads();

    const int warp = tid >> 5, lane = tid & 31;
    {
        const int row = warp >> 2, grp = warp & 3;
        const float4* t4 = (const float4*)(sh + row * 1024);
#pragma unroll 1
        for (int j = 0; j < 16; ++j) {
            const int o = grp * 16 + j;
            const float4* w4 = (const float4*)(a.W + (size_t)o * a.wld);
            float acc = 0.f;
#pragma unroll
            for (int i = 0; i < 8; ++i) {
                float4 wv = w4[lane + (i << 5)];
                float4 tv = t4[lane + (i << 5)];
                acc = fmaf(wv.x, tv.x, fmaf(wv.y, tv.y,
                      fmaf(wv.z, tv.z, fmaf(wv.w, tv.w, acc))));
            }
#pragma unroll
            for (int off = 16; off > 0; off >>= 1)
                acc += __shfl_xor_sync(0xffffffffu, acc, off);
            if (lane == 0) slog[row * 64 + o] = acc + a.bias[o];
        }
    }
    __syncthreads();

    if (warp < 2) {
        float v0 = slog[warp * 64 + lane], v1 = slog[warp * 64 + lane + 32];
        float m = fmaxf(v0, v1);
#pragma unroll
        for (int off = 16; off > 0; off >>= 1)
            m = fmaxf(m, __shfl_xor_sync(0xffffffffu, m, off));
        float e0 = expf(v0 - m), e1 = expf(v1 - m);
        float s = e0 + e1;
#pragma unroll
        for (int off = 16; off > 0; off >>= 1)
            s += __shfl_xor_sync(0xffffffffu, s, off);
        float inv = 1.f / s;
        sw[warp * 64 + lane] = e0 * inv;
        sw[warp * 64 + lane + 32] = e1 * inv;
    }
    __syncthreads();

    // P[b,:] = sum_s w[s] * encW[b,s,:]
    const int row = tid >> 7, tl = tid & 127;
    const float4* e4 = (const float4*)(a.encW + (size_t)(b0 + row) * 65536);
    const float* wrow = sw + row * 64;
#pragma unroll
    for (int rep = 0; rep < 2; ++rep) {
        const int d4 = tl + (rep << 7);
        float4 acc = make_float4(0.f, 0.f, 0.f, 0.f);
#pragma unroll 8
        for (int s = 0; s < SS; ++s) {
            float w = wrow[s];
            float4 ev = e4[s * 256 + d4];
            acc.x = fmaf(w, ev.x, acc.x);
            acc.y = fmaf(w, ev.y, acc.y);
            acc.z = fmaf(w, ev.z, acc.z);
            acc.w = fmaf(w, ev.w, acc.w);
        }
        *(float4*)&a.P[(size_t)(b0 + row) * 1024 + d4 * 4] = acc;
    }
}

// ---------------------------------------------------------------------------
// K2: gruin = relu(P + (t>0 ? U : bc)) -> split bf16
// ---------------------------------------------------------------------------
__global__ __launch_bounds__(256) void gruin_kernel(
    const float* __restrict__ P, const float* __restrict__ U,
    const float* __restrict__ bc, int t,
    __nv_bfloat16* __restrict__ ghi, __nv_bfloat16* __restrict__ glo)
{
    const int i = blockIdx.x * 256 + threadIdx.x;
    const float add = (t > 0) ? U[i] : bc[i & 1023];
    const float v = fmaxf(P[i] + add, 0.f);
    split2(v, ghi[i], glo[i]);
}

// ---------------------------------------------------------------------------
// K4: GRU gates -> h (fp32 + split) + Hall[b][t]
// ---------------------------------------------------------------------------
__global__ __launch_bounds__(256) void gate_kernel(
    const float* __restrict__ gi, const float* __restrict__ gh,
    float* __restrict__ h,
    __nv_bfloat16* __restrict__ hhi, __nv_bfloat16* __restrict__ hlo,
    __nv_bfloat16* __restrict__ Hhi, __nv_bfloat16* __restrict__ Hlo, int t)
{
    const int i = blockIdx.x * 256 + threadIdx.x;
    const int b = i >> 10, d = i & 1023;
    const size_t base = (size_t)b * 3072 + d;
    float r = 1.f / (1.f + expf(-(gi[base] + gh[base])));
    float z = 1.f / (1.f + expf(-(gi[base + 1024] + gh[base + 1024])));
    float n = tanhf(gi[base + 2048] + r * gh[base + 2048]);
    float hn = (1.f - z) * n + z * h[i];
    h[i] = hn;
    __nv_bfloat16 hi, lo;
    split2(hn, hi, lo);
    hhi[i] = hi; hlo[i] = lo;
    const size_t hidx = ((size_t)b * 128 + t) * 1024 + d;
    Hhi[hidx] = hi; Hlo[hidx] = lo;
}

// ---------------------------------------------------------------------------
// Mega setup: all splits, transpose, folds, init in ONE launch
// ---------------------------------------------------------------------------
struct SetupArgs {
    const float *Wih, *Whh, *Wo, *Wc, *enc, *Wa, *ba, *bo, *bc, *hid;
    __nv_bfloat16 *Wih_hi, *Wih_lo, *Whh_hi, *Whh_lo, *Wo_hi, *Wo_lo;
    __nv_bfloat16 *WoT_hi, *WoT_lo, *Wc1_hi, *Wc1_lo, *WcB_hi, *WcB_lo;
    __nv_bfloat16 *enc_hi, *enc_lo, *hhi, *hlo;
    float *WaF, *baF, *bcF, *h;
};

#define MS_N0 12288   // Wih
#define MS_N1 12288   // Whh
#define MS_N2 4096    // Wo
#define MS_N3 1024    // WoT transpose
#define MS_N4 4096    // Wc1
#define MS_N5 4096    // WcB (Wc2)
#define MS_N6 131072  // enc
#define MS_N7 64      // fold_wa
#define MS_N8 128     // fold_bc
#define MS_N9 2048    // init h
#define MS_TOTAL (MS_N0+MS_N1+MS_N2+MS_N3+MS_N4+MS_N5+MS_N6+MS_N7+MS_N8+MS_N9)

__global__ __launch_bounds__(256) void mega_setup_kernel(SetupArgs a)
{
    __shared__ float sbuf[1088];
    int b = blockIdx.x;
    const int tid = threadIdx.x;

    if (b < MS_N0) {                                      // split Wih
        int i = b * 256 + tid;
        split2(a.Wih[i], a.Wih_hi[i], a.Wih_lo[i]);
        return;
    }
    b -= MS_N0;
    if (b < MS_N1) {                                      // split Whh
        int i = b * 256 + tid;
        split2(a.Whh[i], a.Whh_hi[i], a.Whh_lo[i]);
        return;
    }
    b -= MS_N1;
    if (b < MS_N2) {                                      // split Wo
        int i = b * 256 + tid;
        split2(a.Wo[i], a.Wo_hi[i], a.Wo_lo[i]);
        return;
    }
    b -= MS_N2;
    if (b < MS_N3) {                                      // transpose+split Wo
        const int bx = (b & 31) * 32, by = (b >> 5) * 32;
        const int tx = tid & 31, ty = tid >> 5;           // ty 0..7
#pragma unroll
        for (int r = 0; r < 4; ++r)
            sbuf[(ty + 8 * r) * 33 + tx] =
                a.Wo[(size_t)(by + ty + 8 * r) * 1024 + bx + tx];
        __syncthreads();
#pragma unroll
        for (int r = 0; r < 4; ++r) {
            float v = sbuf[tx * 33 + ty + 8 * r];
            size_t o = (size_t)(bx + ty + 8 * r) * 1024 + by + tx;
            split2(v, a.WoT_hi[o], a.WoT_lo[o]);
        }
        return;
    }
    b -= MS_N3;
    if (b < MS_N4) {                                      // split Wc col0 -> Wc1
        int i = b * 256 + tid;
        int r = i >> 10, c = i & 1023;
        split2(a.Wc[(size_t)r * 2048 + c], a.Wc1_hi[i], a.Wc1_lo[i]);
        return;
    }
    b -= MS_N4;
    if (b < MS_N5) {                                      // split Wc col1 -> WcB
        int i = b * 256 + tid;
        int r = i >> 10, c = i & 1023;
        split2(a.Wc[(size_t)r * 2048 + 1024 + c], a.WcB_hi[i], a.WcB_lo[i]);
        return;
    }
    b -= MS_N5;
    if (b < MS_N6) {                                      // split enc
        size_t i = (size_t)b * 256 + tid;
        split2(a.enc[i], a.enc_hi[i], a.enc_lo[i]);
        return;
    }
    b -= MS_N6;
    if (b < MS_N7) {                                      // fold Wa
        const int o = b;
        for (int i = tid; i < 1024; i += 256) sbuf[i] = a.Wa[(size_t)o * 2048 + i];
        __syncthreads();
        for (int j = tid; j < 1024; j += 256) {
            float acc = a.Wa[(size_t)o * 2048 + 1024 + j];
            for (int k = 0; k < 1024; ++k)
                acc = fmaf(sbuf[k], a.Wo[(size_t)k * 1024 + j], acc);
            a.WaF[(size_t)o * 1024 + j] = acc;
        }
        if (tid < 32) {
            float s = 0.f;
            for (int k = tid; k < 1024; k += 32) s += sbuf[k] * a.bo[k];
#pragma unroll
            for (int off = 16; off > 0; off >>= 1)
                s += __shfl_xor_sync(0xffffffffu, s, off);
            if (tid == 0) a.baF[o] = a.ba[o] + s;
        }
        return;
    }
    b -= MS_N7;
    if (b < MS_N8) {                                      // fold bc
        const int n = b * 8 + (tid >> 5);
        const int lane = tid & 31;
        float s = 0.f;
        for (int k = lane; k < 1024; k += 32)
            s += a.Wc[(size_t)n * 2048 + k] * a.bo[k];
#pragma unroll
        for (int off = 16; off > 0; off >>= 1)
            s += __shfl_xor_sync(0xffffffffu, s, off);
        if (lane == 0) a.bcF[n] = a.bc[n] + s;
        return;
    }
    b -= MS_N8;
    {                                                     // init h
        int i = b * 256 + tid;
        float v = a.hid[i];
        a.h[i] = v;
        split2(v, a.hhi[i], a.hlo[i]);
    }
}

__global__ void copyf_kernel(const float* __restrict__ s, float* __restrict__ d, int n)
{
    int i = blockIdx.x * 256 + threadIdx.x;
    if (i < n) d[i] = s[i];
}

// ---------------------------------------------------------------------------
extern "C" void kernel_launch(void* const* d_in, const int* in_sizes, int n_in,
                              void* d_out, int out_size)
{
    const float* enc = (const float*)d_in[0];
    const float* hid = (const float*)d_in[1];
    const float* Wa  = (const float*)d_in[3];
    const float* ba  = (const float*)d_in[4];
    const float* Wc  = (const float*)d_in[5];
    const float* bc  = (const float*)d_in[6];
    const float* Wih = (const float*)d_in[7];
    const float* Whh = (const float*)d_in[8];
    const float* bih = (const float*)d_in[9];
    const float* bhh = (const float*)d_in[10];
    const float* Wo  = (const float*)d_in[11];
    const float* bo  = (const float*)d_in[12];

    float* outseq = (float*)d_out;
    float* outh   = outseq + (size_t)BB * TT * OO;

    // resolve symbols
    __nv_bfloat16 *pWih_hi, *pWih_lo, *pWhh_hi, *pWhh_lo, *pWo_hi, *pWo_lo;
    __nv_bfloat16 *pWoT_hi, *pWoT_lo, *pWc1_hi, *pWc1_lo, *pWcB_hi, *pWcB_lo;
    __nv_bfloat16 *pWcF_hi, *pWcF_lo, *penc_hi, *penc_lo;
    __nv_bfloat16 *pgr_hi, *pgr_lo, *phhi, *phlo, *pH_hi, *pH_lo;
    float *ph, *pgi, *pgh, *pzero, *pWaF, *pbaF, *pbcF, *pencW, *pP, *pU;
    cudaGetSymbolAddress((void**)&pWih_hi, g_Wih_hi); cudaGetSymbolAddress((void**)&pWih_lo, g_Wih_lo);
    cudaGetSymbolAddress((void**)&pWhh_hi, g_Whh_hi); cudaGetSymbolAddress((void**)&pWhh_lo, g_Whh_lo);
    cudaGetSymbolAddress((void**)&pWo_hi, g_Wo_hi);   cudaGetSymbolAddress((void**)&pWo_lo, g_Wo_lo);
    cudaGetSymbolAddress((void**)&pWoT_hi, g_WoT_hi); cudaGetSymbolAddress((void**)&pWoT_lo, g_WoT_lo);
    cudaGetSymbolAddress((void**)&pWc1_hi, g_Wc1_hi); cudaGetSymbolAddress((void**)&pWc1_lo, g_Wc1_lo);
    cudaGetSymbolAddress((void**)&pWcB_hi, g_WcB_hi); cudaGetSymbolAddress((void**)&pWcB_lo, g_WcB_lo);
    cudaGetSymbolAddress((void**)&pWcF_hi, g_WcF_hi); cudaGetSymbolAddress((void**)&pWcF_lo, g_WcF_lo);
    cudaGetSymbolAddress((void**)&penc_hi, g_enc_hi); cudaGetSymbolAddress((void**)&penc_lo, g_enc_lo);
    cudaGetSymbolAddress((void**)&pgr_hi, g_gr_hi);   cudaGetSymbolAddress((void**)&pgr_lo, g_gr_lo);
    cudaGetSymbolAddress((void**)&phhi, g_hhi);       cudaGetSymbolAddress((void**)&phlo, g_hlo);
    cudaGetSymbolAddress((void**)&pH_hi, g_Hall_hi);  cudaGetSymbolAddress((void**)&pH_lo, g_Hall_lo);
    cudaGetSymbolAddress((void**)&ph, g_h);
    cudaGetSymbolAddress((void**)&pgi, g_gi);
    cudaGetSymbolAddress((void**)&pgh, g_gh);
    cudaGetSymbolAddress((void**)&pzero, g_zero);
    cudaGetSymbolAddress((void**)&pWaF, g_WaF);
    cudaGetSymbolAddress((void**)&pbaF, g_baF);
    cudaGetSymbolAddress((void**)&pbcF, g_bcF);
    cudaGetSymbolAddress((void**)&pencW, g_encW);
    cudaGetSymbolAddress((void**)&pP, g_P);
    cudaGetSymbolAddress((void**)&pU, g_U);

    cudaFuncSetAttribute(gemm_std_kernel, cudaFuncAttributeMaxDynamicSharedMemorySize, ENG_SMEM);
    cudaFuncSetAttribute(step1_kernel, cudaFuncAttributeMaxDynamicSharedMemorySize, ENG_SMEM);

    // ---- launch 1: mega setup ----
    {
        SetupArgs s{};
        s.Wih = Wih; s.Whh = Whh; s.Wo = Wo; s.Wc = Wc; s.enc = enc;
        s.Wa = Wa; s.ba = ba; s.bo = bo; s.bc = bc; s.hid = hid;
        s.Wih_hi = pWih_hi; s.Wih_lo = pWih_lo; s.Whh_hi = pWhh_hi; s.Whh_lo = pWhh_lo;
        s.Wo_hi = pWo_hi; s.Wo_lo = pWo_lo; s.WoT_hi = pWoT_hi; s.WoT_lo = pWoT_lo;
        s.Wc1_hi = pWc1_hi; s.Wc1_lo = pWc1_lo; s.WcB_hi = pWcB_hi; s.WcB_lo = pWcB_lo;
        s.enc_hi = penc_hi; s.enc_lo = penc_lo; s.hhi = phhi; s.hlo = phlo;
        s.WaF = pWaF; s.baF = pbaF; s.bcF = pbcF; s.h = ph;
        mega_setup_kernel<<<MS_TOTAL, 256>>>(s);
    }

    // ---- launch 2: encW = enc @ Wc2^T (M=32768) ----
    {
        GP2 P{};
        P.p[0] = { penc_hi, penc_lo, 1024, pWcB_hi, pWcB_lo, 1024, 1024,
                   pzero, pencW, 1024, nullptr, nullptr, 0, 0 };
        gemm_std_kernel<<<dim3(8, 512, 1), 256, ENG_SMEM>>>(P);
    }

    // ---- launch 3: WcF = Wc1 @ Wo (M=1024) -> split ----
    {
        GP2 P{};
        P.p[0] = { pWc1_hi, pWc1_lo, 1024, pWoT_hi, pWoT_lo, 1024, 1024,
                   pzero, nullptr, 0, pWcF_hi, pWcF_lo, 1024, 2 };
        gemm_std_kernel<<<dim3(8, 16, 1), 256, ENG_SMEM>>>(P);
    }

    // ---- decode loop ----
    for (int t = 0; t < TT; ++t) {
        // K1: gh + U + attention->P
        {
            K1Args a{};
            a.gh = { phhi, phlo, 1024, pWhh_hi, pWhh_lo, 1024, 1024,
                     bhh, pgh, 3072, nullptr, nullptr, 0, 0 };
            a.U  = { phhi, phlo, 1024, pWcF_hi, pWcF_lo, 1024, 1024,
                     pbcF, pU, 1024, nullptr, nullptr, 0, 0 };
            a.h = ph; a.encW = pencW;
            a.W = (t == 0) ? (Wa + 1024) : pWaF;
            a.wld = (t == 0) ? 2048 : 1024;
            a.bias = (t == 0) ? ba : pbaF;
            a.P = pP;
            step1_kernel<<<512, 256, ENG_SMEM>>>(a);
        }
        // K2: gruin
        gruin_kernel<<<BB * HH / 256, 256>>>(pP, pU, bc, t, pgr_hi, pgr_lo);
        // K3: gi = gruin @ Wih^T + bih
        {
            GP2 P{};
            P.p[0] = { pgr_hi, pgr_lo, 1024, pWih_hi, pWih_lo, 1024, 1024,
                       bih, pgi, 3072, nullptr, nullptr, 0, 0 };
            gemm_std_kernel<<<dim3(24, 8, 1), 256, ENG_SMEM>>>(P);
        }
        // K4: gates
        gate_kernel<<<BB * HH / 256, 256>>>(pgi, pgh, ph, phhi, phlo, pH_hi, pH_lo, t);
    }

    // ---- final: outseq = Hall @ Wo^T + bo (M = 65536) ----
    {
        GP2 P{};
        P.p[0] = { pH_hi, pH_lo, 1024, pWo_hi, pWo_lo, 1024, 1024,
                   bo, outseq, 1024, nullptr, nullptr, 0, 0 };
        gemm_std_kernel<<<dim3(8, 1024, 1), 256, ENG_SMEM>>>(P);
    }

    if (out_size >= BB * TT * OO + BB * HH) {
        copyf_kernel<<<BB * HH / 256, 256>>>(ph, outh, BB * HH);
    }
}

// round 8
// speedup vs baseline: 1.5336x; 1.5336x over previous
#include <cuda_runtime.h>
#include <cuda_bf16.h>
#include <cstdint>

#define BB 512
#define HH 1024
#define SS 64
#define TT 128

// ---------------------------------------------------------------------------
// Device-global scratch (allocation-free)
// ---------------------------------------------------------------------------
__device__ __align__(256) __nv_bfloat16 g_Wih_hi[3072 * 1024], g_Wih_lo[3072 * 1024];
__device__ __align__(256) __nv_bfloat16 g_Whh_hi[3072 * 1024], g_Whh_lo[3072 * 1024];
__device__ __align__(256) __nv_bfloat16 g_Wo_hi[1024 * 1024], g_Wo_lo[1024 * 1024];
__device__ __align__(256) __nv_bfloat16 g_WoT_hi[1024 * 1024], g_WoT_lo[1024 * 1024];
__device__ __align__(256) __nv_bfloat16 g_Wc1_hi[1024 * 1024], g_Wc1_lo[1024 * 1024];
__device__ __align__(256) __nv_bfloat16 g_WcB_hi[1024 * 1024], g_WcB_lo[1024 * 1024];
__device__ __align__(256) __nv_bfloat16 g_WcF_hi[1024 * 1024], g_WcF_lo[1024 * 1024];
__device__ __align__(256) __nv_bfloat16 g_enc_hi[(size_t)32768 * 1024];
__device__ __align__(256) __nv_bfloat16 g_enc_lo[(size_t)32768 * 1024];
__device__ __align__(256) float g_WaF[64 * 1024];
__device__ __align__(256) float g_baF[64];
__device__ __align__(256) float g_bcF[1024];
__device__ __align__(256) float g_biasGhU[4096];
// packed operands for engine v4 (pre-swizzled slabs)
// W slab: (ntile,kst) -> 32768 B  [hi 16K | lo 16K], rows 128 x cols 64
// A slab: (mtile,kst) -> 16384 B  [hi 8K | lo 8K],  rows 64  x cols 64
__device__ __align__(256) char g_WihP[24 * 16 * 32768];
__device__ __align__(256) char g_WhhUP[32 * 16 * 32768];     // [Whh(3072) | WcF(1024)]
__device__ __align__(256) char g_WoP[8 * 16 * 32768];
__device__ __align__(256) char g_grP[8 * 16 * 16384];        // gruin packed
__device__ __align__(256) char g_hP[8 * 16 * 16384];         // h packed
__device__ __align__(256) char g_HallP[(size_t)1024 * 16 * 16384];  // all h_t packed
// fp32 activations
__device__ __align__(256) float g_encW[(size_t)32768 * 1024];
__device__ __align__(256) float g_P[512 * 1024];
__device__ __align__(256) float g_h[512 * 1024];
__device__ __align__(256) float g_ghU[512 * 4096];           // [gh(3072) | U(1024)]
__device__ __align__(256) float g_gi[512 * 3072];
__device__ __align__(256) float g_zero[4096];

// ---------------------------------------------------------------------------
// Helpers
// ---------------------------------------------------------------------------
__device__ __forceinline__ void split2(float v, __nv_bfloat16& hi, __nv_bfloat16& lo) {
    hi = __float2bfloat16(v);
    lo = __float2bfloat16(v - __bfloat162float(hi));
}

__device__ __host__ __forceinline__ uint32_t swz(uint32_t off) {
    return off ^ ((off >> 3) & 0x70);
}
__device__ __forceinline__ size_t pa_off(int mt, int ks, int row, int col2) {
    return (size_t)(mt * 16 + ks) * 16384 + swz((uint32_t)(row * 128 + col2));
}
__device__ __forceinline__ size_t pw_off(int nt, int ks, int row, int col2) {
    return (size_t)(nt * 16 + ks) * 32768 + swz((uint32_t)(row * 128 + col2));
}

__device__ __forceinline__ uint32_t smem_u32(const void* p) {
    uint32_t a;
    asm("{ .reg .u64 t; cvta.to.shared.u64 t, %1; cvt.u32.u64 %0, t; }" : "=r"(a) : "l"(p));
    return a;
}

__device__ __forceinline__ void ldsm_x4(uint32_t* r, uint32_t addr) {
    asm volatile("ldmatrix.sync.aligned.m8n8.x4.shared.b16 {%0,%1,%2,%3}, [%4];\n"
                 : "=r"(r[0]), "=r"(r[1]), "=r"(r[2]), "=r"(r[3]) : "r"(addr));
}

__device__ __forceinline__ void mma_bf16(float* c, const uint32_t* a, const uint32_t* b) {
    asm volatile(
        "mma.sync.aligned.m16n8k16.row.col.f32.bf16.bf16.f32 "
        "{%0,%1,%2,%3}, {%4,%5,%6,%7}, {%8,%9}, {%0,%1,%2,%3};\n"
        : "+f"(c[0]), "+f"(c[1]), "+f"(c[2]), "+f"(c[3])
        : "r"(a[0]), "r"(a[1]), "r"(a[2]), "r"(a[3]), "r"(b[0]), "r"(b[1]));
}

__device__ __forceinline__ void cp16a(uint32_t dst, const void* src) {
    asm volatile("cp.async.cg.shared.global [%0], [%1], 16;\n" :: "r"(dst), "l"(src));
}
#define CP_COMMIT() asm volatile("cp.async.commit_group;\n" ::: "memory")
#define CP_WAIT1()  asm volatile("cp.async.wait_group 1;\n" ::: "memory")

#define MBAR_INIT(mb, c) asm volatile("mbarrier.init.shared.b64 [%0], %1;" :: "r"((uint32_t)(mb)), "r"((uint32_t)(c)) : "memory")
#define EXPECT_TX(mb, n) asm volatile("mbarrier.arrive.expect_tx.shared.b64 _, [%0], %1;" :: "r"((uint32_t)(mb)), "r"((uint32_t)(n)) : "memory")
#define BULK_CP(dst, src, n, mb) \
    asm volatile("cp.async.bulk.shared::cluster.global.mbarrier::complete_tx::bytes [%0], [%1], %2, [%3];" \
        :: "r"((uint32_t)(dst)), "l"(src), "r"((uint32_t)(n)), "r"((uint32_t)(mb)) : "memory")

#define MBAR_WAIT(mb, par) do { \
    uint32_t _m = (uint32_t)(mb); uint32_t _p = (uint32_t)(par); uint32_t _d; \
    asm volatile("{\n\t.reg .pred p;\n\t" \
        "mbarrier.try_wait.parity.acquire.cta.shared::cta.b64 p, [%1], %2;\n\t" \
        "selp.b32 %0, 1, 0, p;\n\t}" : "=r"(_d) : "r"(_m), "r"(_p) : "memory"); \
    if (!_d) { \
        asm volatile("{\n\t.reg .pred P1;\n\t" \
            "WL_%=:\n\t" \
            "mbarrier.try_wait.parity.acquire.cta.shared::cta.b64 P1, [%0], %1, 0x989680;\n\t" \
            "@P1 bra.uni WD_%=;\n\t" \
            "bra.uni WL_%=;\n\t" \
            "WD_%=:\n\t}" :: "r"(_m), "r"(_p) : "memory"); \
    } \
} while (0)

// ---------------------------------------------------------------------------
// Engine v3 (cp.async 16B path) — setup GEMMs only (encW, WcF).
// ---------------------------------------------------------------------------
struct GProb {
    const __nv_bfloat16 *Ahi, *Alo; int lda;
    const __nv_bfloat16 *Whi, *Wlo; int ldw;
    int K;
    const float* bias;
    float* Cf; int ldc;
    __nv_bfloat16 *Chi, *Clo; int ldch;
    int mode;
};

#define ENG_ALO 9216u
#define ENG_WHI 18432u
#define ENG_WLO 36864u
#define ENG_STAGE 55296u
#define ENG_SMEM 110592

__global__ __launch_bounds__(256, 2) void gemm_std_kernel(GProb p)
{
    extern __shared__ char sm[];
    const uint32_t smbase = smem_u32(sm);
    const int tid = threadIdx.x, warp = tid >> 5, lane = tid & 31;
    const int m0 = blockIdx.y * 64, n0 = blockIdx.x * 128;
    const int S = p.K >> 6;
    const int wm = warp >> 2, wn = warp & 3;
    const int lr = tid >> 1;
    const int lc = (tid & 1) * 4;

    float acc[2][4][4];
#pragma unroll
    for (int mi = 0; mi < 2; ++mi)
#pragma unroll
        for (int nf = 0; nf < 4; ++nf)
#pragma unroll
            for (int q = 0; q < 4; ++q) acc[mi][nf][q] = 0.f;

    const __nv_bfloat16* abase = (lr < 64)
        ? p.Ahi + (size_t)(m0 + lr) * p.lda
        : p.Alo + (size_t)(m0 + lr - 64) * p.lda;
    const __nv_bfloat16* w1base = p.Whi + (size_t)(n0 + lr) * p.ldw;
    const __nv_bfloat16* w2base = p.Wlo + (size_t)(n0 + lr) * p.ldw;
    const uint32_t rowb = (uint32_t)lr * 144 + (uint32_t)lc * 16;

    auto load_stage = [&](int s) {
        const int k0 = (s << 6) + lc * 8;
        const uint32_t sb = smbase + (uint32_t)(s & 1) * ENG_STAGE;
#pragma unroll
        for (int c = 0; c < 4; ++c) cp16a(sb + rowb + c * 16, abase + k0 + c * 8);
#pragma unroll
        for (int c = 0; c < 4; ++c) cp16a(sb + ENG_WHI + rowb + c * 16, w1base + k0 + c * 8);
#pragma unroll
        for (int c = 0; c < 4; ++c) cp16a(sb + ENG_WLO + rowb + c * 16, w2base + k0 + c * 8);
    };

    load_stage(0); CP_COMMIT();
    load_stage(1); CP_COMMIT();

    const int arow = wm * 32 + (lane & 15);
    const int acolb = (lane >> 4) << 3;
    const int g = lane >> 3;
    const int brow = wn * 32 + ((g >> 1) << 3) + (lane & 7);
    const int bcolb = (g & 1) << 3;

    for (int s = 0; s < S; ++s) {
        CP_WAIT1();
        __syncthreads();
        const uint32_t sb = smbase + (uint32_t)(s & 1) * ENG_STAGE;
#pragma unroll
        for (int kk = 0; kk < 4; ++kk) {
            const int acol = kk * 16 + acolb;
            uint32_t ahi[2][4], alo[2][4];
#pragma unroll
            for (int mi = 0; mi < 2; ++mi) {
                const uint32_t off = (uint32_t)((arow + mi * 16) * 144 + acol * 2);
                ldsm_x4(ahi[mi], sb + off);
                ldsm_x4(alo[mi], sb + ENG_ALO + off);
            }
            const int bcol = kk * 16 + bcolb;
            uint32_t bhi[4][2], blo[4][2];
#pragma unroll
            for (int nh = 0; nh < 2; ++nh) {
                uint32_t r[4];
                const uint32_t off = (uint32_t)((brow + nh * 16) * 144 + bcol * 2);
                ldsm_x4(r, sb + ENG_WHI + off);
                bhi[nh * 2 + 0][0] = r[0]; bhi[nh * 2 + 0][1] = r[1];
                bhi[nh * 2 + 1][0] = r[2]; bhi[nh * 2 + 1][1] = r[3];
                ldsm_x4(r, sb + ENG_WLO + off);
                blo[nh * 2 + 0][0] = r[0]; blo[nh * 2 + 0][1] = r[1];
                blo[nh * 2 + 1][0] = r[2]; blo[nh * 2 + 1][1] = r[3];
            }
#pragma unroll
            for (int mi = 0; mi < 2; ++mi)
#pragma unroll
                for (int nf = 0; nf < 4; ++nf)
                    mma_bf16(acc[mi][nf], ahi[mi], bhi[nf]);
#pragma unroll
            for (int mi = 0; mi < 2; ++mi)
#pragma unroll
                for (int nf = 0; nf < 4; ++nf)
                    mma_bf16(acc[mi][nf], ahi[mi], blo[nf]);
#pragma unroll
            for (int mi = 0; mi < 2; ++mi)
#pragma unroll
                for (int nf = 0; nf < 4; ++nf)
                    mma_bf16(acc[mi][nf], alo[mi], bhi[nf]);
        }
        __syncthreads();
        if (s + 2 < S) load_stage(s + 2);
        CP_COMMIT();
    }

    const int row0 = m0 + wm * 32 + (lane >> 2);
    const int col0 = n0 + wn * 32 + ((lane & 3) << 1);
#pragma unroll
    for (int mi = 0; mi < 2; ++mi) {
#pragma unroll
        for (int nf = 0; nf < 4; ++nf) {
            const int col = col0 + nf * 8;
            const float b0 = p.bias[col], b1 = p.bias[col + 1];
#pragma unroll
            for (int half = 0; half < 2; ++half) {
                const int row = row0 + mi * 16 + half * 8;
                float v0 = acc[mi][nf][half * 2 + 0] + b0;
                float v1 = acc[mi][nf][half * 2 + 1] + b1;
                if (p.mode == 0) {
                    *(float2*)&p.Cf[(size_t)row * p.ldc + col] = make_float2(v0, v1);
                } else {
                    __nv_bfloat162 hv, lv;
                    split2(v0, hv.x, lv.x); split2(v1, hv.y, lv.y);
                    *(__nv_bfloat162*)&p.Chi[(size_t)row * p.ldch + col] = hv;
                    *(__nv_bfloat162*)&p.Clo[(size_t)row * p.ldch + col] = lv;
                }
            }
        }
    }
}

// ---------------------------------------------------------------------------
// v4 GEMM block body: packed operands, cp.async.bulk, K=1024 (16 stages).
// smem: 2 x 49152 B dynamic. fp32 out + bias.
// ---------------------------------------------------------------------------
#define V4_SMEM 98304

__device__ __forceinline__ void gemm4_block(
    const char* __restrict__ Apack, const char* __restrict__ Wpack,
    const float* __restrict__ bias, float* __restrict__ Cf, int ldc,
    int mtile, int ntile, uint32_t sb0, uint32_t mbb)
{
    const int tid = threadIdx.x, warp = tid >> 5, lane = tid & 31;
    const char* Ab = Apack + (size_t)mtile * 16 * 16384;
    const char* Wb = Wpack + (size_t)ntile * 16 * 32768;
    const uint32_t mb[2] = { mbb, mbb + 8 };

    if (tid == 0) { MBAR_INIT(mb[0], 1); MBAR_INIT(mb[1], 1); }
    __syncthreads();

    auto issue = [&](int s) {
        const uint32_t dst = sb0 + (uint32_t)(s & 1) * 49152u;
        EXPECT_TX(mb[s & 1], 49152u);
        BULK_CP(dst, Ab + (size_t)s * 16384, 16384u, mb[s & 1]);
        BULK_CP(dst + 16384u, Wb + (size_t)s * 32768, 32768u, mb[s & 1]);
    };
    if (tid == 0) { issue(0); issue(1); }

    const int wm = warp >> 2, wn = warp & 3;
    const int arow = wm * 32 + (lane & 15);
    const int acolb = (lane >> 4) << 3;
    const int g = lane >> 3;
    const int brow = wn * 32 + ((g >> 1) << 3) + (lane & 7);
    const int bcolb = (g & 1) << 3;

    float acc[2][4][4];
#pragma unroll
    for (int mi = 0; mi < 2; ++mi)
#pragma unroll
        for (int nf = 0; nf < 4; ++nf)
#pragma unroll
            for (int q = 0; q < 4; ++q) acc[mi][nf][q] = 0.f;

    for (int s = 0; s < 16; ++s) {
        const int b = s & 1;
        MBAR_WAIT(mb[b], (s >> 1) & 1);
        const uint32_t sa = sb0 + (uint32_t)b * 49152u;
        const uint32_t sw = sa + 16384u;
#pragma unroll
        for (int kk = 0; kk < 4; ++kk) {
            const int acol = kk * 16 + acolb;
            uint32_t ahi[2][4], alo[2][4];
#pragma unroll
            for (int mi = 0; mi < 2; ++mi) {
                const uint32_t off = swz((uint32_t)((arow + mi * 16) * 128 + acol * 2));
                ldsm_x4(ahi[mi], sa + off);
                ldsm_x4(alo[mi], sa + 8192u + off);
            }
            const int bcol = kk * 16 + bcolb;
            uint32_t bhi[4][2], blo[4][2];
#pragma unroll
            for (int nh = 0; nh < 2; ++nh) {
                uint32_t r[4];
                const uint32_t off = swz((uint32_t)((brow + nh * 16) * 128 + bcol * 2));
                ldsm_x4(r, sw + off);
                bhi[nh * 2 + 0][0] = r[0]; bhi[nh * 2 + 0][1] = r[1];
                bhi[nh * 2 + 1][0] = r[2]; bhi[nh * 2 + 1][1] = r[3];
                ldsm_x4(r, sw + 16384u + off);
                blo[nh * 2 + 0][0] = r[0]; blo[nh * 2 + 0][1] = r[1];
                blo[nh * 2 + 1][0] = r[2]; blo[nh * 2 + 1][1] = r[3];
            }
#pragma unroll
            for (int mi = 0; mi < 2; ++mi)
#pragma unroll
                for (int nf = 0; nf < 4; ++nf)
                    mma_bf16(acc[mi][nf], ahi[mi], bhi[nf]);
#pragma unroll
            for (int mi = 0; mi < 2; ++mi)
#pragma unroll
                for (int nf = 0; nf < 4; ++nf)
                    mma_bf16(acc[mi][nf], ahi[mi], blo[nf]);
#pragma unroll
            for (int mi = 0; mi < 2; ++mi)
#pragma unroll
                for (int nf = 0; nf < 4; ++nf)
                    mma_bf16(acc[mi][nf], alo[mi], bhi[nf]);
        }
        __syncthreads();
        if (tid == 0 && s + 2 < 16) issue(s + 2);
    }

    const int row0 = mtile * 64 + wm * 32 + (lane >> 2);
    const int col0 = ntile * 128 + wn * 32 + ((lane & 3) << 1);
#pragma unroll
    for (int mi = 0; mi < 2; ++mi) {
#pragma unroll
        for (int nf = 0; nf < 4; ++nf) {
            const int col = col0 + nf * 8;
            const float b0 = bias[col], b1 = bias[col + 1];
#pragma unroll
            for (int half = 0; half < 2; ++half) {
                const int row = row0 + mi * 16 + half * 8;
                *(float2*)&Cf[(size_t)row * ldc + col] =
                    make_float2(acc[mi][nf][half * 2 + 0] + b0,
                                acc[mi][nf][half * 2 + 1] + b1);
            }
        }
    }
}

__global__ __launch_bounds__(256, 2) void gemm4_kernel(
    const char* __restrict__ Apack, const char* __restrict__ Wpack,
    const float* __restrict__ bias, float* __restrict__ Cf, int ldc)
{
    extern __shared__ char sm[];
    __shared__ uint64_t mbar[2];
    gemm4_block(Apack, Wpack, bias, Cf, ldc, blockIdx.y, blockIdx.x,
                smem_u32(sm), smem_u32(&mbar[0]));
}

// ---------------------------------------------------------------------------
// stepA: blocks 0..255 = ghU v4 GEMM (ntile=bid&31, mtile=bid>>5);
//        blocks 256..767 = attention row (b = bid-256).
// Single launch: GEMM fills the chip first, attention backfills (overlap).
// ---------------------------------------------------------------------------
struct StepAArgs {
    const char *hP, *WhhUP;
    const float* biasG;
    float* ghU;
    const float *h, *encW, *W, *bias;   // attention
    int wld;
    float* P;
};

__global__ __launch_bounds__(256, 2) void stepA_kernel(StepAArgs a)
{
    extern __shared__ char sm[];
    __shared__ uint64_t mbar[2];
    __shared__ float sh[1024];
    __shared__ float slog[64];
    __shared__ float sw[64];

    const int bid = blockIdx.x;
    if (bid < 256) {
        gemm4_block(a.hP, a.WhhUP, a.biasG, a.ghU, 4096,
                    bid >> 5, bid & 31, smem_u32(sm), smem_u32(&mbar[0]));
        return;
    }

    // ---- attention: one batch row ----
    const int tid = threadIdx.x, warp = tid >> 5, lane = tid & 31;
    const int b = bid - 256;

    *(float4*)&sh[tid * 4] = *(const float4*)&a.h[(size_t)b * 1024 + tid * 4];
    __syncthreads();

#pragma unroll 1
    for (int j = 0; j < 8; ++j) {
        const int o = warp * 8 + j;
        const float4* w4 = (const float4*)(a.W + (size_t)o * a.wld);
        const float4* t4 = (const float4*)sh;
        float acc = 0.f;
#pragma unroll
        for (int i = 0; i < 8; ++i) {
            float4 wv = w4[lane + (i << 5)];
            float4 tv = t4[lane + (i << 5)];
            acc = fmaf(wv.x, tv.x, fmaf(wv.y, tv.y,
                  fmaf(wv.z, tv.z, fmaf(wv.w, tv.w, acc))));
        }
#pragma unroll
        for (int off = 16; off > 0; off >>= 1)
            acc += __shfl_xor_sync(0xffffffffu, acc, off);
        if (lane == 0) slog[o] = acc + a.bias[o];
    }
    __syncthreads();

    if (warp == 0) {
        float v0 = slog[lane], v1 = slog[lane + 32];
        float m = fmaxf(v0, v1);
#pragma unroll
        for (int off = 16; off > 0; off >>= 1)
            m = fmaxf(m, __shfl_xor_sync(0xffffffffu, m, off));
        float e0 = expf(v0 - m), e1 = expf(v1 - m);
        float s = e0 + e1;
#pragma unroll
        for (int off = 16; off > 0; off >>= 1)
            s += __shfl_xor_sync(0xffffffffu, s, off);
        float inv = 1.f / s;
        sw[lane] = e0 * inv;
        sw[lane + 32] = e1 * inv;
    }
    __syncthreads();

    const float4* e4 = (const float4*)(a.encW + (size_t)b * 65536);
    float4 acc = make_float4(0.f, 0.f, 0.f, 0.f);
#pragma unroll 8
    for (int s = 0; s < SS; ++s) {
        float w = sw[s];
        float4 ev = e4[s * 256 + tid];
        acc.x = fmaf(w, ev.x, acc.x);
        acc.y = fmaf(w, ev.y, acc.y);
        acc.z = fmaf(w, ev.z, acc.z);
        acc.w = fmaf(w, ev.w, acc.w);
    }
    *(float4*)&a.P[(size_t)b * 1024 + tid * 4] = acc;
}

// ---------------------------------------------------------------------------
// gruin = relu(P + (t>0 ? U : bc)) -> packed split bf16
// ---------------------------------------------------------------------------
__global__ __launch_bounds__(256) void gruin_kernel(
    const float* __restrict__ P, const float* __restrict__ ghU,
    const float* __restrict__ bc, int t, char* __restrict__ grP)
{
    const int e = (blockIdx.x * 256 + threadIdx.x) * 2;
    const int m = e >> 10, d = e & 1023;
    float a0, a1;
    if (t > 0) {
        const float* u = ghU + (size_t)m * 4096 + 3072 + d;
        a0 = u[0]; a1 = u[1];
    } else { a0 = bc[d]; a1 = bc[d + 1]; }
    float v0 = fmaxf(P[e] + a0, 0.f);
    float v1 = fmaxf(P[e + 1] + a1, 0.f);
    __nv_bfloat162 hv, lv;
    split2(v0, hv.x, lv.x); split2(v1, hv.y, lv.y);
    const size_t off = pa_off(m >> 6, d >> 6, m & 63, (d & 63) * 2);
    *(__nv_bfloat162*)(grP + off) = hv;
    *(__nv_bfloat162*)(grP + off + 8192) = lv;
}

// ---------------------------------------------------------------------------
// GRU gates -> h (fp32), h packed, Hall packed
// ---------------------------------------------------------------------------
__global__ __launch_bounds__(256) void gate_kernel(
    const float* __restrict__ gi, const float* __restrict__ ghU,
    float* __restrict__ h, char* __restrict__ hP, char* __restrict__ HallP, int t)
{
    const int e = (blockIdx.x * 256 + threadIdx.x) * 2;
    const int m = e >> 10, d = e & 1023;
    float hn[2];
#pragma unroll
    for (int j = 0; j < 2; ++j) {
        const size_t b3 = (size_t)m * 3072 + d + j;
        const size_t b4 = (size_t)m * 4096 + d + j;
        float r = 1.f / (1.f + expf(-(gi[b3] + ghU[b4])));
        float z = 1.f / (1.f + expf(-(gi[b3 + 1024] + ghU[b4 + 1024])));
        float n = tanhf(gi[b3 + 2048] + r * ghU[b4 + 2048]);
        hn[j] = (1.f - z) * n + z * h[e + j];
    }
    *(float2*)&h[e] = make_float2(hn[0], hn[1]);
    __nv_bfloat162 hv, lv;
    split2(hn[0], hv.x, lv.x); split2(hn[1], hv.y, lv.y);
    const size_t off = pa_off(m >> 6, d >> 6, m & 63, (d & 63) * 2);
    *(__nv_bfloat162*)(hP + off) = hv;
    *(__nv_bfloat162*)(hP + off + 8192) = lv;
    const int M = m * 128 + t;
    const size_t hoff = pa_off(M >> 6, d >> 6, M & 63, (d & 63) * 2);
    *(__nv_bfloat162*)(HallP + hoff) = hv;
    *(__nv_bfloat162*)(HallP + hoff + 8192) = lv;
}

// ---------------------------------------------------------------------------
// Weight pack
// ---------------------------------------------------------------------------
__global__ __launch_bounds__(256) void pack_w_kernel(
    const __nv_bfloat16* __restrict__ hi, const __nv_bfloat16* __restrict__ lo,
    int nrows, char* __restrict__ dst, int row_base)
{
    const int e = (blockIdx.x * 256 + threadIdx.x) * 2;
    const int n = e >> 10, k = e & 1023;
    if (n >= nrows) return;
    const int N = n + row_base;
    const size_t off = pw_off(N >> 7, k >> 6, N & 127, (k & 63) * 2);
    *(__nv_bfloat162*)(dst + off) = *(const __nv_bfloat162*)(hi + (size_t)n * 1024 + k);
    *(__nv_bfloat162*)(dst + off + 16384) = *(const __nv_bfloat162*)(lo + (size_t)n * 1024 + k);
}

__global__ void build_bias_kernel(const float* __restrict__ bhh,
                                  const float* __restrict__ bcF,
                                  float* __restrict__ out)
{
    int i = blockIdx.x * 256 + threadIdx.x;
    out[i] = (i < 3072) ? bhh[i] : bcF[i - 3072];
}

// ---------------------------------------------------------------------------
// Mega setup
// ---------------------------------------------------------------------------
struct SetupArgs {
    const float *Wih, *Whh, *Wo, *Wc, *enc, *Wa, *ba, *bo, *bc, *hid;
    __nv_bfloat16 *Wih_hi, *Wih_lo, *Whh_hi, *Whh_lo, *Wo_hi, *Wo_lo;
    __nv_bfloat16 *WoT_hi, *WoT_lo, *Wc1_hi, *Wc1_lo, *WcB_hi, *WcB_lo;
    __nv_bfloat16 *enc_hi, *enc_lo;
    float *WaF, *baF, *bcF, *h;
    char* hP;
};

#define MS_N0 12288
#define MS_N1 12288
#define MS_N2 4096
#define MS_N3 1024
#define MS_N4 4096
#define MS_N5 4096
#define MS_N6 131072
#define MS_N7 64
#define MS_N8 128
#define MS_N9 2048
#define MS_TOTAL (MS_N0+MS_N1+MS_N2+MS_N3+MS_N4+MS_N5+MS_N6+MS_N7+MS_N8+MS_N9)

__global__ __launch_bounds__(256) void mega_setup_kernel(SetupArgs a)
{
    __shared__ float sbuf[1088];
    int b = blockIdx.x;
    const int tid = threadIdx.x;

    if (b < MS_N0) { int i = b * 256 + tid; split2(a.Wih[i], a.Wih_hi[i], a.Wih_lo[i]); return; }
    b -= MS_N0;
    if (b < MS_N1) { int i = b * 256 + tid; split2(a.Whh[i], a.Whh_hi[i], a.Whh_lo[i]); return; }
    b -= MS_N1;
    if (b < MS_N2) { int i = b * 256 + tid; split2(a.Wo[i], a.Wo_hi[i], a.Wo_lo[i]); return; }
    b -= MS_N2;
    if (b < MS_N3) {
        const int bx = (b & 31) * 32, by = (b >> 5) * 32;
        const int tx = tid & 31, ty = tid >> 5;
#pragma unroll
        for (int r = 0; r < 4; ++r)
            sbuf[(ty + 8 * r) * 33 + tx] = a.Wo[(size_t)(by + ty + 8 * r) * 1024 + bx + tx];
        __syncthreads();
#pragma unroll
        for (int r = 0; r < 4; ++r) {
            float v = sbuf[tx * 33 + ty + 8 * r];
            size_t o = (size_t)(bx + ty + 8 * r) * 1024 + by + tx;
            split2(v, a.WoT_hi[o], a.WoT_lo[o]);
        }
        return;
    }
    b -= MS_N3;
    if (b < MS_N4) {
        int i = b * 256 + tid; int r = i >> 10, c = i & 1023;
        split2(a.Wc[(size_t)r * 2048 + c], a.Wc1_hi[i], a.Wc1_lo[i]);
        return;
    }
    b -= MS_N4;
    if (b < MS_N5) {
        int i = b * 256 + tid; int r = i >> 10, c = i & 1023;
        split2(a.Wc[(size_t)r * 2048 + 1024 + c], a.WcB_hi[i], a.WcB_lo[i]);
        return;
    }
    b -= MS_N5;
    if (b < MS_N6) {
        size_t i = (size_t)b * 256 + tid;
        split2(a.enc[i], a.enc_hi[i], a.enc_lo[i]);
        return;
    }
    b -= MS_N6;
    if (b < MS_N7) {
        const int o = b;
        for (int i = tid; i < 1024; i += 256) sbuf[i] = a.Wa[(size_t)o * 2048 + i];
        __syncthreads();
        for (int j = tid; j < 1024; j += 256) {
            float acc = a.Wa[(size_t)o * 2048 + 1024 + j];
            for (int k = 0; k < 1024; ++k)
                acc = fmaf(sbuf[k], a.Wo[(size_t)k * 1024 + j], acc);
            a.WaF[(size_t)o * 1024 + j] = acc;
        }
        if (tid < 32) {
            float s = 0.f;
            for (int k = tid; k < 1024; k += 32) s += sbuf[k] * a.bo[k];
#pragma unroll
            for (int off = 16; off > 0; off >>= 1)
                s += __shfl_xor_sync(0xffffffffu, s, off);
            if (tid == 0) a.baF[o] = a.ba[o] + s;
        }
        return;
    }
    b -= MS_N7;
    if (b < MS_N8) {
        const int n = b * 8 + (tid >> 5);
        const int lane = tid & 31;
        float s = 0.f;
        for (int k = lane; k < 1024; k += 32) s += a.Wc[(size_t)n * 2048 + k] * a.bo[k];
#pragma unroll
        for (int off = 16; off > 0; off >>= 1)
            s += __shfl_xor_sync(0xffffffffu, s, off);
        if (lane == 0) a.bcF[n] = a.bc[n] + s;
        return;
    }
    b -= MS_N8;
    {
        int i = b * 256 + tid;
        int m = i >> 10, d = i & 1023;
        float v = a.hid[i];
        a.h[i] = v;
        __nv_bfloat16 hi, lo;
        split2(v, hi, lo);
        const size_t off = pa_off(m >> 6, d >> 6, m & 63, (d & 63) * 2);
        *(__nv_bfloat16*)(a.hP + off) = hi;
        *(__nv_bfloat16*)(a.hP + off + 8192) = lo;
    }
}

__global__ void copyf_kernel(const float* __restrict__ s, float* __restrict__ d, int n)
{
    int i = blockIdx.x * 256 + threadIdx.x;
    if (i < n) d[i] = s[i];
}

// ---------------------------------------------------------------------------
extern "C" void kernel_launch(void* const* d_in, const int* in_sizes, int n_in,
                              void* d_out, int out_size)
{
    const float* enc = (const float*)d_in[0];
    const float* hid = (const float*)d_in[1];
    const float* Wa  = (const float*)d_in[3];
    const float* ba  = (const float*)d_in[4];
    const float* Wc  = (const float*)d_in[5];
    const float* bc  = (const float*)d_in[6];
    const float* Wih = (const float*)d_in[7];
    const float* Whh = (const float*)d_in[8];
    const float* bih = (const float*)d_in[9];
    const float* bhh = (const float*)d_in[10];
    const float* Wo  = (const float*)d_in[11];
    const float* bo  = (const float*)d_in[12];

    float* outseq = (float*)d_out;
    float* outh   = outseq + (size_t)BB * TT * HH;

    __nv_bfloat16 *pWih_hi, *pWih_lo, *pWhh_hi, *pWhh_lo, *pWo_hi, *pWo_lo;
    __nv_bfloat16 *pWoT_hi, *pWoT_lo, *pWc1_hi, *pWc1_lo, *pWcB_hi, *pWcB_lo;
    __nv_bfloat16 *pWcF_hi, *pWcF_lo, *penc_hi, *penc_lo;
    char *pWihP, *pWhhUP, *pWoP, *pgrP, *phP, *pHallP;
    float *ph, *pgi, *pghU, *pzero, *pWaF, *pbaF, *pbcF, *pbiasG, *pencW, *pP;
    cudaGetSymbolAddress((void**)&pWih_hi, g_Wih_hi); cudaGetSymbolAddress((void**)&pWih_lo, g_Wih_lo);
    cudaGetSymbolAddress((void**)&pWhh_hi, g_Whh_hi); cudaGetSymbolAddress((void**)&pWhh_lo, g_Whh_lo);
    cudaGetSymbolAddress((void**)&pWo_hi, g_Wo_hi);   cudaGetSymbolAddress((void**)&pWo_lo, g_Wo_lo);
    cudaGetSymbolAddress((void**)&pWoT_hi, g_WoT_hi); cudaGetSymbolAddress((void**)&pWoT_lo, g_WoT_lo);
    cudaGetSymbolAddress((void**)&pWc1_hi, g_Wc1_hi); cudaGetSymbolAddress((void**)&pWc1_lo, g_Wc1_lo);
    cudaGetSymbolAddress((void**)&pWcB_hi, g_WcB_hi); cudaGetSymbolAddress((void**)&pWcB_lo, g_WcB_lo);
    cudaGetSymbolAddress((void**)&pWcF_hi, g_WcF_hi); cudaGetSymbolAddress((void**)&pWcF_lo, g_WcF_lo);
    cudaGetSymbolAddress((void**)&penc_hi, g_enc_hi); cudaGetSymbolAddress((void**)&penc_lo, g_enc_lo);
    cudaGetSymbolAddress((void**)&pWihP, g_WihP);     cudaGetSymbolAddress((void**)&pWhhUP, g_WhhUP);
    cudaGetSymbolAddress((void**)&pWoP, g_WoP);       cudaGetSymbolAddress((void**)&pgrP, g_grP);
    cudaGetSymbolAddress((void**)&phP, g_hP);         cudaGetSymbolAddress((void**)&pHallP, g_HallP);
    cudaGetSymbolAddress((void**)&ph, g_h);           cudaGetSymbolAddress((void**)&pgi, g_gi);
    cudaGetSymbolAddress((void**)&pghU, g_ghU);       cudaGetSymbolAddress((void**)&pzero, g_zero);
    cudaGetSymbolAddress((void**)&pWaF, g_WaF);       cudaGetSymbolAddress((void**)&pbaF, g_baF);
    cudaGetSymbolAddress((void**)&pbcF, g_bcF);       cudaGetSymbolAddress((void**)&pbiasG, g_biasGhU);
    cudaGetSymbolAddress((void**)&pencW, g_encW);     cudaGetSymbolAddress((void**)&pP, g_P);

    cudaFuncSetAttribute(gemm_std_kernel, cudaFuncAttributeMaxDynamicSharedMemorySize, ENG_SMEM);
    cudaFuncSetAttribute(gemm4_kernel, cudaFuncAttributeMaxDynamicSharedMemorySize, V4_SMEM);
    cudaFuncSetAttribute(stepA_kernel, cudaFuncAttributeMaxDynamicSharedMemorySize, V4_SMEM);

    // ---- setup ----
    {
        SetupArgs s{};
        s.Wih = Wih; s.Whh = Whh; s.Wo = Wo; s.Wc = Wc; s.enc = enc;
        s.Wa = Wa; s.ba = ba; s.bo = bo; s.bc = bc; s.hid = hid;
        s.Wih_hi = pWih_hi; s.Wih_lo = pWih_lo; s.Whh_hi = pWhh_hi; s.Whh_lo = pWhh_lo;
        s.Wo_hi = pWo_hi; s.Wo_lo = pWo_lo; s.WoT_hi = pWoT_hi; s.WoT_lo = pWoT_lo;
        s.Wc1_hi = pWc1_hi; s.Wc1_lo = pWc1_lo; s.WcB_hi = pWcB_hi; s.WcB_lo = pWcB_lo;
        s.enc_hi = penc_hi; s.enc_lo = penc_lo;
        s.WaF = pWaF; s.baF = pbaF; s.bcF = pbcF; s.h = ph; s.hP = phP;
        mega_setup_kernel<<<MS_TOTAL, 256>>>(s);
    }
    {
        GProb p = { penc_hi, penc_lo, 1024, pWcB_hi, pWcB_lo, 1024, 1024,
                    pzero, pencW, 1024, nullptr, nullptr, 0, 0 };
        gemm_std_kernel<<<dim3(8, 512), 256, ENG_SMEM>>>(p);
    }
    {
        GProb p = { pWc1_hi, pWc1_lo, 1024, pWoT_hi, pWoT_lo, 1024, 1024,
                    pzero, nullptr, 0, pWcF_hi, pWcF_lo, 1024, 2 };
        gemm_std_kernel<<<dim3(8, 16), 256, ENG_SMEM>>>(p);
    }
    pack_w_kernel<<<3072 * 1024 / 512, 256>>>(pWih_hi, pWih_lo, 3072, pWihP, 0);
    pack_w_kernel<<<3072 * 1024 / 512, 256>>>(pWhh_hi, pWhh_lo, 3072, pWhhUP, 0);
    pack_w_kernel<<<1024 * 1024 / 512, 256>>>(pWcF_hi, pWcF_lo, 1024, pWhhUP, 3072);
    pack_w_kernel<<<1024 * 1024 / 512, 256>>>(pWo_hi, pWo_lo, 1024, pWoP, 0);
    build_bias_kernel<<<16, 256>>>(bhh, pbcF, pbiasG);

    // ---- decode loop (single stream) ----
    for (int t = 0; t < TT; ++t) {
        // stepA: ghU GEMM (256 blocks) + attention->P (512 blocks), one launch
        {
            StepAArgs a{};
            a.hP = phP; a.WhhUP = pWhhUP; a.biasG = pbiasG; a.ghU = pghU;
            a.h = ph; a.encW = pencW;
            a.W = (t == 0) ? (Wa + 1024) : pWaF;
            a.wld = (t == 0) ? 2048 : 1024;
            a.bias = (t == 0) ? ba : pbaF;
            a.P = pP;
            stepA_kernel<<<768, 256, V4_SMEM>>>(a);
        }
        gruin_kernel<<<BB * HH / 512, 256>>>(pP, pghU, bc, t, pgrP);
        gemm4_kernel<<<dim3(24, 8), 256, V4_SMEM>>>(pgrP, pWihP, bih, pgi, 3072);
        gate_kernel<<<BB * HH / 512, 256>>>(pgi, pghU, ph, phP, pHallP, t);
    }

    // ---- final: outseq = Hall @ Wo^T + bo (M = 65536) ----
    gemm4_kernel<<<dim3(8, 1024), 256, V4_SMEM>>>(pHallP, pWoP, bo, outseq, 1024);

    if (out_size >= BB * TT * HH + BB * HH) {
        copyf_kernel<<<BB * HH / 256, 256>>>(ph, outh, BB * HH);
    }
}

// round 9
// speedup vs baseline: 1.6218x; 1.0575x over previous
#include <cuda_runtime.h>
#include <cuda_bf16.h>
#include <cstdint>

#define BB 512
#define HH 1024
#define SS 64
#define TT 128

// ---------------------------------------------------------------------------
// Device-global scratch (allocation-free)
// ---------------------------------------------------------------------------
// linear splits (only what the v3 setup GEMM needs)
__device__ __align__(256) __nv_bfloat16 g_WoT_hi[1024 * 1024], g_WoT_lo[1024 * 1024];
__device__ __align__(256) __nv_bfloat16 g_Wc1_hi[1024 * 1024], g_Wc1_lo[1024 * 1024];
__device__ __align__(256) __nv_bfloat16 g_WcF_hi[1024 * 1024], g_WcF_lo[1024 * 1024];
// folded attention weights
__device__ __align__(256) float g_WaF[64 * 1024];
__device__ __align__(256) float g_baF[64];
__device__ __align__(256) float g_biasGhU[4096];
// packed v4 slabs:  W slab (ntile,ks) -> 32768 B [hi|lo], rows 128 x cols 64
//                   A slab (mtile,ks) -> 16384 B [hi|lo], rows 64 x cols 64
__device__ __align__(256) char g_WihP[24 * 16 * 32768];
__device__ __align__(256) char g_WhhUP[32 * 16 * 32768];     // [Whh(3072) | WcF(1024)]
__device__ __align__(256) char g_WoP[8 * 16 * 32768];
__device__ __align__(256) char g_WcBP[8 * 16 * 32768];
__device__ __align__(256) char g_encP[(size_t)512 * 16 * 16384];
__device__ __align__(256) char g_grP[8 * 16 * 16384];
__device__ __align__(256) char g_hP[8 * 16 * 16384];
__device__ __align__(256) char g_HallP[(size_t)1024 * 16 * 16384];
// fp32 activations
__device__ __align__(256) float g_encW[(size_t)32768 * 1024];
__device__ __align__(256) float g_P[512 * 1024];
__device__ __align__(256) float g_h[512 * 1024];
__device__ __align__(256) float g_ghU[512 * 4096];           // [gh(3072) | U(1024)]
__device__ __align__(256) float g_gi[512 * 3072];
__device__ __align__(256) float g_zero[4096];

// ---------------------------------------------------------------------------
// Helpers
// ---------------------------------------------------------------------------
__device__ __forceinline__ void split2(float v, __nv_bfloat16& hi, __nv_bfloat16& lo) {
    hi = __float2bfloat16(v);
    lo = __float2bfloat16(v - __bfloat162float(hi));
}

__device__ __host__ __forceinline__ uint32_t swz(uint32_t off) {
    return off ^ ((off >> 3) & 0x70);
}
__device__ __forceinline__ size_t pa_off(int mt, int ks, int row, int col2) {
    return (size_t)(mt * 16 + ks) * 16384 + swz((uint32_t)(row * 128 + col2));
}
__device__ __forceinline__ size_t pw_off(int nt, int ks, int row, int col2) {
    return (size_t)(nt * 16 + ks) * 32768 + swz((uint32_t)(row * 128 + col2));
}

__device__ __forceinline__ uint32_t smem_u32(const void* p) {
    uint32_t a;
    asm("{ .reg .u64 t; cvta.to.shared.u64 t, %1; cvt.u32.u64 %0, t; }" : "=r"(a) : "l"(p));
    return a;
}

__device__ __forceinline__ void ldsm_x4(uint32_t* r, uint32_t addr) {
    asm volatile("ldmatrix.sync.aligned.m8n8.x4.shared.b16 {%0,%1,%2,%3}, [%4];\n"
                 : "=r"(r[0]), "=r"(r[1]), "=r"(r[2]), "=r"(r[3]) : "r"(addr));
}

__device__ __forceinline__ void mma_bf16(float* c, const uint32_t* a, const uint32_t* b) {
    asm volatile(
        "mma.sync.aligned.m16n8k16.row.col.f32.bf16.bf16.f32 "
        "{%0,%1,%2,%3}, {%4,%5,%6,%7}, {%8,%9}, {%0,%1,%2,%3};\n"
        : "+f"(c[0]), "+f"(c[1]), "+f"(c[2]), "+f"(c[3])
        : "r"(a[0]), "r"(a[1]), "r"(a[2]), "r"(a[3]), "r"(b[0]), "r"(b[1]));
}

__device__ __forceinline__ void cp16a(uint32_t dst, const void* src) {
    asm volatile("cp.async.cg.shared.global [%0], [%1], 16;\n" :: "r"(dst), "l"(src));
}
#define CP_COMMIT() asm volatile("cp.async.commit_group;\n" ::: "memory")
#define CP_WAIT1()  asm volatile("cp.async.wait_group 1;\n" ::: "memory")

#define MBAR_INIT(mb, c) asm volatile("mbarrier.init.shared.b64 [%0], %1;" :: "r"((uint32_t)(mb)), "r"((uint32_t)(c)) : "memory")
#define EXPECT_TX(mb, n) asm volatile("mbarrier.arrive.expect_tx.shared.b64 _, [%0], %1;" :: "r"((uint32_t)(mb)), "r"((uint32_t)(n)) : "memory")
#define BULK_CP(dst, src, n, mb) \
    asm volatile("cp.async.bulk.shared::cluster.global.mbarrier::complete_tx::bytes [%0], [%1], %2, [%3];" \
        :: "r"((uint32_t)(dst)), "l"(src), "r"((uint32_t)(n)), "r"((uint32_t)(mb)) : "memory")

#define MBAR_WAIT(mb, par) do { \
    uint32_t _m = (uint32_t)(mb); uint32_t _p = (uint32_t)(par); uint32_t _d; \
    asm volatile("{\n\t.reg .pred p;\n\t" \
        "mbarrier.try_wait.parity.acquire.cta.shared::cta.b64 p, [%1], %2;\n\t" \
        "selp.b32 %0, 1, 0, p;\n\t}" : "=r"(_d) : "r"(_m), "r"(_p) : "memory"); \
    if (!_d) { \
        asm volatile("{\n\t.reg .pred P1;\n\t" \
            "WL_%=:\n\t" \
            "mbarrier.try_wait.parity.acquire.cta.shared::cta.b64 P1, [%0], %1, 0x989680;\n\t" \
            "@P1 bra.uni WD_%=;\n\t" \
            "bra.uni WL_%=;\n\t" \
            "WD_%=:\n\t}" :: "r"(_m), "r"(_p) : "memory"); \
    } \
} while (0)

// ---------------------------------------------------------------------------
// Engine v3 (cp.async 16B path) — setup WcF GEMM only.
// ---------------------------------------------------------------------------
struct GProb {
    const __nv_bfloat16 *Ahi, *Alo; int lda;
    const __nv_bfloat16 *Whi, *Wlo; int ldw;
    int K;
    const float* bias;
    float* Cf; int ldc;
    __nv_bfloat16 *Chi, *Clo; int ldch;
    int mode;
};

#define ENG_ALO 9216u
#define ENG_WHI 18432u
#define ENG_WLO 36864u
#define ENG_STAGE 55296u
#define ENG_SMEM 110592

__global__ __launch_bounds__(256, 2) void gemm_std_kernel(GProb p)
{
    extern __shared__ char sm[];
    const uint32_t smbase = smem_u32(sm);
    const int tid = threadIdx.x, warp = tid >> 5, lane = tid & 31;
    const int m0 = blockIdx.y * 64, n0 = blockIdx.x * 128;
    const int S = p.K >> 6;
    const int wm = warp >> 2, wn = warp & 3;
    const int lr = tid >> 1;
    const int lc = (tid & 1) * 4;

    float acc[2][4][4];
#pragma unroll
    for (int mi = 0; mi < 2; ++mi)
#pragma unroll
        for (int nf = 0; nf < 4; ++nf)
#pragma unroll
            for (int q = 0; q < 4; ++q) acc[mi][nf][q] = 0.f;

    const __nv_bfloat16* abase = (lr < 64)
        ? p.Ahi + (size_t)(m0 + lr) * p.lda
        : p.Alo + (size_t)(m0 + lr - 64) * p.lda;
    const __nv_bfloat16* w1base = p.Whi + (size_t)(n0 + lr) * p.ldw;
    const __nv_bfloat16* w2base = p.Wlo + (size_t)(n0 + lr) * p.ldw;
    const uint32_t rowb = (uint32_t)lr * 144 + (uint32_t)lc * 16;

    auto load_stage = [&](int s) {
        const int k0 = (s << 6) + lc * 8;
        const uint32_t sb = smbase + (uint32_t)(s & 1) * ENG_STAGE;
#pragma unroll
        for (int c = 0; c < 4; ++c) cp16a(sb + rowb + c * 16, abase + k0 + c * 8);
#pragma unroll
        for (int c = 0; c < 4; ++c) cp16a(sb + ENG_WHI + rowb + c * 16, w1base + k0 + c * 8);
#pragma unroll
        for (int c = 0; c < 4; ++c) cp16a(sb + ENG_WLO + rowb + c * 16, w2base + k0 + c * 8);
    };

    load_stage(0); CP_COMMIT();
    load_stage(1); CP_COMMIT();

    const int arow = wm * 32 + (lane & 15);
    const int acolb = (lane >> 4) << 3;
    const int g = lane >> 3;
    const int brow = wn * 32 + ((g >> 1) << 3) + (lane & 7);
    const int bcolb = (g & 1) << 3;

    for (int s = 0; s < S; ++s) {
        CP_WAIT1();
        __syncthreads();
        const uint32_t sb = smbase + (uint32_t)(s & 1) * ENG_STAGE;
#pragma unroll
        for (int kk = 0; kk < 4; ++kk) {
            const int acol = kk * 16 + acolb;
            uint32_t ahi[2][4], alo[2][4];
#pragma unroll
            for (int mi = 0; mi < 2; ++mi) {
                const uint32_t off = (uint32_t)((arow + mi * 16) * 144 + acol * 2);
                ldsm_x4(ahi[mi], sb + off);
                ldsm_x4(alo[mi], sb + ENG_ALO + off);
            }
            const int bcol = kk * 16 + bcolb;
            uint32_t bhi[4][2], blo[4][2];
#pragma unroll
            for (int nh = 0; nh < 2; ++nh) {
                uint32_t r[4];
                const uint32_t off = (uint32_t)((brow + nh * 16) * 144 + bcol * 2);
                ldsm_x4(r, sb + ENG_WHI + off);
                bhi[nh * 2 + 0][0] = r[0]; bhi[nh * 2 + 0][1] = r[1];
                bhi[nh * 2 + 1][0] = r[2]; bhi[nh * 2 + 1][1] = r[3];
                ldsm_x4(r, sb + ENG_WLO + off);
                blo[nh * 2 + 0][0] = r[0]; blo[nh * 2 + 0][1] = r[1];
                blo[nh * 2 + 1][0] = r[2]; blo[nh * 2 + 1][1] = r[3];
            }
#pragma unroll
            for (int mi = 0; mi < 2; ++mi)
#pragma unroll
                for (int nf = 0; nf < 4; ++nf)
                    mma_bf16(acc[mi][nf], ahi[mi], bhi[nf]);
#pragma unroll
            for (int mi = 0; mi < 2; ++mi)
#pragma unroll
                for (int nf = 0; nf < 4; ++nf)
                    mma_bf16(acc[mi][nf], ahi[mi], blo[nf]);
#pragma unroll
            for (int mi = 0; mi < 2; ++mi)
#pragma unroll
                for (int nf = 0; nf < 4; ++nf)
                    mma_bf16(acc[mi][nf], alo[mi], bhi[nf]);
        }
        __syncthreads();
        if (s + 2 < S) load_stage(s + 2);
        CP_COMMIT();
    }

    const int row0 = m0 + wm * 32 + (lane >> 2);
    const int col0 = n0 + wn * 32 + ((lane & 3) << 1);
#pragma unroll
    for (int mi = 0; mi < 2; ++mi) {
#pragma unroll
        for (int nf = 0; nf < 4; ++nf) {
            const int col = col0 + nf * 8;
            const float b0 = p.bias[col], b1 = p.bias[col + 1];
#pragma unroll
            for (int half = 0; half < 2; ++half) {
                const int row = row0 + mi * 16 + half * 8;
                float v0 = acc[mi][nf][half * 2 + 0] + b0;
                float v1 = acc[mi][nf][half * 2 + 1] + b1;
                if (p.mode == 0) {
                    *(float2*)&p.Cf[(size_t)row * p.ldc + col] = make_float2(v0, v1);
                } else {
                    __nv_bfloat162 hv, lv;
                    split2(v0, hv.x, lv.x); split2(v1, hv.y, lv.y);
                    *(__nv_bfloat162*)&p.Chi[(size_t)row * p.ldch + col] = hv;
                    *(__nv_bfloat162*)&p.Clo[(size_t)row * p.ldch + col] = lv;
                }
            }
        }
    }
}

// ---------------------------------------------------------------------------
// v4 GEMM block body: packed operands, cp.async.bulk, K=1024 (16 stages).
// ---------------------------------------------------------------------------
#define V4_SMEM 98304

__device__ __forceinline__ void gemm4_block(
    const char* __restrict__ Apack, const char* __restrict__ Wpack,
    const float* __restrict__ bias, float* __restrict__ Cf, int ldc,
    int mtile, int ntile, uint32_t sb0, uint32_t mbb)
{
    const int tid = threadIdx.x, warp = tid >> 5, lane = tid & 31;
    const char* Ab = Apack + (size_t)mtile * 16 * 16384;
    const char* Wb = Wpack + (size_t)ntile * 16 * 32768;
    const uint32_t mb[2] = { mbb, mbb + 8 };

    if (tid == 0) { MBAR_INIT(mb[0], 1); MBAR_INIT(mb[1], 1); }
    __syncthreads();

    auto issue = [&](int s) {
        const uint32_t dst = sb0 + (uint32_t)(s & 1) * 49152u;
        EXPECT_TX(mb[s & 1], 49152u);
        BULK_CP(dst, Ab + (size_t)s * 16384, 16384u, mb[s & 1]);
        BULK_CP(dst + 16384u, Wb + (size_t)s * 32768, 32768u, mb[s & 1]);
    };
    if (tid == 0) { issue(0); issue(1); }

    const int wm = warp >> 2, wn = warp & 3;
    const int arow = wm * 32 + (lane & 15);
    const int acolb = (lane >> 4) << 3;
    const int g = lane >> 3;
    const int brow = wn * 32 + ((g >> 1) << 3) + (lane & 7);
    const int bcolb = (g & 1) << 3;

    float acc[2][4][4];
#pragma unroll
    for (int mi = 0; mi < 2; ++mi)
#pragma unroll
        for (int nf = 0; nf < 4; ++nf)
#pragma unroll
            for (int q = 0; q < 4; ++q) acc[mi][nf][q] = 0.f;

    for (int s = 0; s < 16; ++s) {
        const int b = s & 1;
        MBAR_WAIT(mb[b], (s >> 1) & 1);
        const uint32_t sa = sb0 + (uint32_t)b * 49152u;
        const uint32_t sw = sa + 16384u;
#pragma unroll
        for (int kk = 0; kk < 4; ++kk) {
            const int acol = kk * 16 + acolb;
            uint32_t ahi[2][4], alo[2][4];
#pragma unroll
            for (int mi = 0; mi < 2; ++mi) {
                const uint32_t off = swz((uint32_t)((arow + mi * 16) * 128 + acol * 2));
                ldsm_x4(ahi[mi], sa + off);
                ldsm_x4(alo[mi], sa + 8192u + off);
            }
            const int bcol = kk * 16 + bcolb;
            uint32_t bhi[4][2], blo[4][2];
#pragma unroll
            for (int nh = 0; nh < 2; ++nh) {
                uint32_t r[4];
                const uint32_t off = swz((uint32_t)((brow + nh * 16) * 128 + bcol * 2));
                ldsm_x4(r, sw + off);
                bhi[nh * 2 + 0][0] = r[0]; bhi[nh * 2 + 0][1] = r[1];
                bhi[nh * 2 + 1][0] = r[2]; bhi[nh * 2 + 1][1] = r[3];
                ldsm_x4(r, sw + 16384u + off);
                blo[nh * 2 + 0][0] = r[0]; blo[nh * 2 + 0][1] = r[1];
                blo[nh * 2 + 1][0] = r[2]; blo[nh * 2 + 1][1] = r[3];
            }
#pragma unroll
            for (int mi = 0; mi < 2; ++mi)
#pragma unroll
                for (int nf = 0; nf < 4; ++nf)
                    mma_bf16(acc[mi][nf], ahi[mi], bhi[nf]);
#pragma unroll
            for (int mi = 0; mi < 2; ++mi)
#pragma unroll
                for (int nf = 0; nf < 4; ++nf)
                    mma_bf16(acc[mi][nf], ahi[mi], blo[nf]);
#pragma unroll
            for (int mi = 0; mi < 2; ++mi)
#pragma unroll
                for (int nf = 0; nf < 4; ++nf)
                    mma_bf16(acc[mi][nf], alo[mi], bhi[nf]);
        }
        __syncthreads();
        if (tid == 0 && s + 2 < 16) issue(s + 2);
    }

    const int row0 = mtile * 64 + wm * 32 + (lane >> 2);
    const int col0 = ntile * 128 + wn * 32 + ((lane & 3) << 1);
#pragma unroll
    for (int mi = 0; mi < 2; ++mi) {
#pragma unroll
        for (int nf = 0; nf < 4; ++nf) {
            const int col = col0 + nf * 8;
            const float b0 = bias[col], b1 = bias[col + 1];
#pragma unroll
            for (int half = 0; half < 2; ++half) {
                const int row = row0 + mi * 16 + half * 8;
                *(float2*)&Cf[(size_t)row * ldc + col] =
                    make_float2(acc[mi][nf][half * 2 + 0] + b0,
                                acc[mi][nf][half * 2 + 1] + b1);
            }
        }
    }
}

// generic v4 launch wrapper; mtile = blockIdx.y * mscale + mbase
__global__ __launch_bounds__(256, 2) void gemm4_kernel(
    const char* __restrict__ Apack, const char* __restrict__ Wpack,
    const float* __restrict__ bias, float* __restrict__ Cf, int ldc,
    int mscale, int mbase)
{
    extern __shared__ char sm[];
    __shared__ uint64_t mbar[2];
    gemm4_block(Apack, Wpack, bias, Cf, ldc,
                blockIdx.y * mscale + mbase, blockIdx.x,
                smem_u32(sm), smem_u32(&mbar[0]));
}

// ---------------------------------------------------------------------------
// stepA: blocks 0..255 = ghU v4 GEMM; blocks 256..767 = attention row.
// ---------------------------------------------------------------------------
struct StepAArgs {
    const char *hP, *WhhUP;
    const float* biasG;
    float* ghU;
    const float *h, *encW, *W, *bias;
    int wld;
    float* P;
};

__global__ __launch_bounds__(256, 2) void stepA_kernel(StepAArgs a)
{
    extern __shared__ char sm[];
    __shared__ uint64_t mbar[2];
    __shared__ float sh[1024];
    __shared__ float slog[64];
    __shared__ float sw[64];

    const int bid = blockIdx.x;
    if (bid < 256) {
        gemm4_block(a.hP, a.WhhUP, a.biasG, a.ghU, 4096,
                    bid >> 5, bid & 31, smem_u32(sm), smem_u32(&mbar[0]));
        return;
    }

    const int tid = threadIdx.x, warp = tid >> 5, lane = tid & 31;
    const int b = bid - 256;

    *(float4*)&sh[tid * 4] = *(const float4*)&a.h[(size_t)b * 1024 + tid * 4];
    __syncthreads();

#pragma unroll 1
    for (int j = 0; j < 8; ++j) {
        const int o = warp * 8 + j;
        const float4* w4 = (const float4*)(a.W + (size_t)o * a.wld);
        const float4* t4 = (const float4*)sh;
        float acc = 0.f;
#pragma unroll
        for (int i = 0; i < 8; ++i) {
            float4 wv = w4[lane + (i << 5)];
            float4 tv = t4[lane + (i << 5)];
            acc = fmaf(wv.x, tv.x, fmaf(wv.y, tv.y,
                  fmaf(wv.z, tv.z, fmaf(wv.w, tv.w, acc))));
        }
#pragma unroll
        for (int off = 16; off > 0; off >>= 1)
            acc += __shfl_xor_sync(0xffffffffu, acc, off);
        if (lane == 0) slog[o] = acc + a.bias[o];
    }
    __syncthreads();

    if (warp == 0) {
        float v0 = slog[lane], v1 = slog[lane + 32];
        float m = fmaxf(v0, v1);
#pragma unroll
        for (int off = 16; off > 0; off >>= 1)
            m = fmaxf(m, __shfl_xor_sync(0xffffffffu, m, off));
        float e0 = expf(v0 - m), e1 = expf(v1 - m);
        float s = e0 + e1;
#pragma unroll
        for (int off = 16; off > 0; off >>= 1)
            s += __shfl_xor_sync(0xffffffffu, s, off);
        float inv = 1.f / s;
        sw[lane] = e0 * inv;
        sw[lane + 32] = e1 * inv;
    }
    __syncthreads();

    const float4* e4 = (const float4*)(a.encW + (size_t)b * 65536);
    float4 acc = make_float4(0.f, 0.f, 0.f, 0.f);
#pragma unroll 8
    for (int s = 0; s < SS; ++s) {
        float w = sw[s];
        float4 ev = e4[s * 256 + tid];
        acc.x = fmaf(w, ev.x, acc.x);
        acc.y = fmaf(w, ev.y, acc.y);
        acc.z = fmaf(w, ev.z, acc.z);
        acc.w = fmaf(w, ev.w, acc.w);
    }
    *(float4*)&a.P[(size_t)b * 1024 + tid * 4] = acc;
}

// ---------------------------------------------------------------------------
// stepB: blocks 0..191 = gi GEMM; blocks 192..255 (t>=64) = early Wo blocks
// on even Hall mtiles (their history t<64 is complete).
// ---------------------------------------------------------------------------
struct StepBArgs {
    const char *grP, *WihP;
    const float* bih;
    float* gi;
    const char *HallP, *WoP;
    const float* bo;
    float* outseq;
    int t;
};

__global__ __launch_bounds__(256, 2) void stepB_kernel(StepBArgs a)
{
    extern __shared__ char sm[];
    __shared__ uint64_t mbar[2];
    const int bid = blockIdx.x;
    if (bid < 192) {
        gemm4_block(a.grP, a.WihP, a.bih, a.gi, 3072,
                    bid / 24, bid % 24, smem_u32(sm), smem_u32(&mbar[0]));
    } else {
        const int idx = (a.t - 64) * 64 + (bid - 192);
        gemm4_block(a.HallP, a.WoP, a.bo, a.outseq, 1024,
                    2 * (idx >> 3), idx & 7, smem_u32(sm), smem_u32(&mbar[0]));
    }
}

// ---------------------------------------------------------------------------
// gruin = relu(P + (t>0 ? U : bc)) -> packed split bf16
// ---------------------------------------------------------------------------
__global__ __launch_bounds__(256) void gruin_kernel(
    const float* __restrict__ P, const float* __restrict__ ghU,
    const float* __restrict__ bc, int t, char* __restrict__ grP)
{
    const int e = (blockIdx.x * 256 + threadIdx.x) * 2;
    const int m = e >> 10, d = e & 1023;
    float a0, a1;
    if (t > 0) {
        const float* u = ghU + (size_t)m * 4096 + 3072 + d;
        a0 = u[0]; a1 = u[1];
    } else { a0 = bc[d]; a1 = bc[d + 1]; }
    float v0 = fmaxf(P[e] + a0, 0.f);
    float v1 = fmaxf(P[e + 1] + a1, 0.f);
    __nv_bfloat162 hv, lv;
    split2(v0, hv.x, lv.x); split2(v1, hv.y, lv.y);
    const size_t off = pa_off(m >> 6, d >> 6, m & 63, (d & 63) * 2);
    *(__nv_bfloat162*)(grP + off) = hv;
    *(__nv_bfloat162*)(grP + off + 8192) = lv;
}

// ---------------------------------------------------------------------------
// GRU gates -> h (fp32), h packed, Hall packed
// ---------------------------------------------------------------------------
__global__ __launch_bounds__(256) void gate_kernel(
    const float* __restrict__ gi, const float* __restrict__ ghU,
    float* __restrict__ h, char* __restrict__ hP, char* __restrict__ HallP, int t)
{
    const int e = (blockIdx.x * 256 + threadIdx.x) * 2;
    const int m = e >> 10, d = e & 1023;
    float hn[2];
#pragma unroll
    for (int j = 0; j < 2; ++j) {
        const size_t b3 = (size_t)m * 3072 + d + j;
        const size_t b4 = (size_t)m * 4096 + d + j;
        float r = 1.f / (1.f + expf(-(gi[b3] + ghU[b4])));
        float z = 1.f / (1.f + expf(-(gi[b3 + 1024] + ghU[b4 + 1024])));
        float n = tanhf(gi[b3 + 2048] + r * ghU[b4 + 2048]);
        hn[j] = (1.f - z) * n + z * h[e + j];
    }
    *(float2*)&h[e] = make_float2(hn[0], hn[1]);
    __nv_bfloat162 hv, lv;
    split2(hn[0], hv.x, lv.x); split2(hn[1], hv.y, lv.y);
    const size_t off = pa_off(m >> 6, d >> 6, m & 63, (d & 63) * 2);
    *(__nv_bfloat162*)(hP + off) = hv;
    *(__nv_bfloat162*)(hP + off + 8192) = lv;
    const int M = m * 128 + t;
    const size_t hoff = pa_off(M >> 6, d >> 6, M & 63, (d & 63) * 2);
    *(__nv_bfloat162*)(HallP + hoff) = hv;
    *(__nv_bfloat162*)(HallP + hoff + 8192) = lv;
}

// ---------------------------------------------------------------------------
// pack (split bf16 hi/lo) from linear bf16 pair into W slab (for WcF)
// ---------------------------------------------------------------------------
__global__ __launch_bounds__(256) void pack_w_kernel(
    const __nv_bfloat16* __restrict__ hi, const __nv_bfloat16* __restrict__ lo,
    int nrows, char* __restrict__ dst, int row_base)
{
    const int e = (blockIdx.x * 256 + threadIdx.x) * 2;
    const int n = e >> 10, k = e & 1023;
    if (n >= nrows) return;
    const int N = n + row_base;
    const size_t off = pw_off(N >> 7, k >> 6, N & 127, (k & 63) * 2);
    *(__nv_bfloat162*)(dst + off) = *(const __nv_bfloat162*)(hi + (size_t)n * 1024 + k);
    *(__nv_bfloat162*)(dst + off + 16384) = *(const __nv_bfloat162*)(lo + (size_t)n * 1024 + k);
}

// ---------------------------------------------------------------------------
// Mega setup: split+pack everything, folds, biasG, init h. One launch.
// ---------------------------------------------------------------------------
struct SetupArgs {
    const float *Wih, *Whh, *Wo, *Wc, *enc, *Wa, *ba, *bo, *bc, *bhh, *hid;
    char *WihP, *WhhUP, *WoP, *WcBP, *encP, *hP;
    __nv_bfloat16 *WoT_hi, *WoT_lo, *Wc1_hi, *Wc1_lo;
    float *WaF, *baF, *biasG, *h;
};

// fp32 row-major -> W slab, 2 elems/thread
__device__ __forceinline__ void pack_w_f32(const float* src, int ld, int i,
                                           char* dst, int row_base)
{
    const int n = i >> 10, k = i & 1023;
    const float v0 = src[(size_t)n * ld + k];
    const float v1 = src[(size_t)n * ld + k + 1];
    __nv_bfloat162 hv, lv;
    split2(v0, hv.x, lv.x); split2(v1, hv.y, lv.y);
    const int N = n + row_base;
    const size_t off = pw_off(N >> 7, k >> 6, N & 127, (k & 63) * 2);
    *(__nv_bfloat162*)(dst + off) = hv;
    *(__nv_bfloat162*)(dst + off + 16384) = lv;
}

#define MS_N0 6144    // pack Wih
#define MS_N1 6144    // pack Whh
#define MS_N2 2048    // pack Wo
#define MS_N3 1024    // WoT transpose+split
#define MS_N4 2048    // Wc1 linear split
#define MS_N5 2048    // pack WcB
#define MS_N6 65536   // pack enc (A layout)
#define MS_N7 64      // fold Wa
#define MS_N8 128     // fold bc -> biasG[3072:]
#define MS_N9 12      // bhh -> biasG[0:3072]
#define MS_N10 1024   // init h
#define MS_TOTAL (MS_N0+MS_N1+MS_N2+MS_N3+MS_N4+MS_N5+MS_N6+MS_N7+MS_N8+MS_N9+MS_N10)

__global__ __launch_bounds__(256) void mega_setup_kernel(SetupArgs a)
{
    __shared__ float sbuf[1088];
    int b = blockIdx.x;
    const int tid = threadIdx.x;

    if (b < MS_N0) { pack_w_f32(a.Wih, 1024, (b * 256 + tid) * 2, a.WihP, 0); return; }
    b -= MS_N0;
    if (b < MS_N1) { pack_w_f32(a.Whh, 1024, (b * 256 + tid) * 2, a.WhhUP, 0); return; }
    b -= MS_N1;
    if (b < MS_N2) { pack_w_f32(a.Wo, 1024, (b * 256 + tid) * 2, a.WoP, 0); return; }
    b -= MS_N2;
    if (b < MS_N3) {                                      // WoT transpose + split
        const int bx = (b & 31) * 32, by = (b >> 5) * 32;
        const int tx = tid & 31, ty = tid >> 5;
#pragma unroll
        for (int r = 0; r < 4; ++r)
            sbuf[(ty + 8 * r) * 33 + tx] = a.Wo[(size_t)(by + ty + 8 * r) * 1024 + bx + tx];
        __syncthreads();
#pragma unroll
        for (int r = 0; r < 4; ++r) {
            float v = sbuf[tx * 33 + ty + 8 * r];
            size_t o = (size_t)(bx + ty + 8 * r) * 1024 + by + tx;
            split2(v, a.WoT_hi[o], a.WoT_lo[o]);
        }
        return;
    }
    b -= MS_N3;
    if (b < MS_N4) {                                      // Wc col0 linear split
        int i = (b * 256 + tid) * 2;
        int r = i >> 10, c = i & 1023;
        split2(a.Wc[(size_t)r * 2048 + c], a.Wc1_hi[i], a.Wc1_lo[i]);
        split2(a.Wc[(size_t)r * 2048 + c + 1], a.Wc1_hi[i + 1], a.Wc1_lo[i + 1]);
        return;
    }
    b -= MS_N4;
    if (b < MS_N5) { pack_w_f32(a.Wc + 1024, 2048, (b * 256 + tid) * 2, a.WcBP, 0); return; }
    b -= MS_N5;
    if (b < MS_N6) {                                      // pack enc (A layout)
        const size_t i = ((size_t)b * 256 + tid) * 2;
        const int M = (int)(i >> 10), k = (int)(i & 1023);
        __nv_bfloat162 hv, lv;
        split2(a.enc[i], hv.x, lv.x);
        split2(a.enc[i + 1], hv.y, lv.y);
        const size_t off = pa_off(M >> 6, k >> 6, M & 63, (k & 63) * 2);
        *(__nv_bfloat162*)(a.encP + off) = hv;
        *(__nv_bfloat162*)(a.encP + off + 8192) = lv;
        return;
    }
    b -= MS_N6;
    if (b < MS_N7) {                                      // fold Wa
        const int o = b;
        for (int i = tid; i < 1024; i += 256) sbuf[i] = a.Wa[(size_t)o * 2048 + i];
        __syncthreads();
        for (int j = tid; j < 1024; j += 256) {
            float acc = a.Wa[(size_t)o * 2048 + 1024 + j];
            for (int k = 0; k < 1024; ++k)
                acc = fmaf(sbuf[k], a.Wo[(size_t)k * 1024 + j], acc);
            a.WaF[(size_t)o * 1024 + j] = acc;
        }
        if (tid < 32) {
            float s = 0.f;
            for (int k = tid; k < 1024; k += 32) s += sbuf[k] * a.bo[k];
#pragma unroll
            for (int off = 16; off > 0; off >>= 1)
                s += __shfl_xor_sync(0xffffffffu, s, off);
            if (tid == 0) a.baF[o] = a.ba[o] + s;
        }
        return;
    }
    b -= MS_N7;
    if (b < MS_N8) {                                      // fold bc -> biasG[3072+n]
        const int n = b * 8 + (tid >> 5);
        const int lane = tid & 31;
        float s = 0.f;
        for (int k = lane; k < 1024; k += 32) s += a.Wc[(size_t)n * 2048 + k] * a.bo[k];
#pragma unroll
        for (int off = 16; off > 0; off >>= 1)
            s += __shfl_xor_sync(0xffffffffu, s, off);
        if (lane == 0) a.biasG[3072 + n] = a.bc[n] + s;
        return;
    }
    b -= MS_N8;
    if (b < MS_N9) {                                      // bhh -> biasG[0:3072]
        int i = b * 256 + tid;
        a.biasG[i] = a.bhh[i];
        return;
    }
    b -= MS_N9;
    {                                                     // init h
        int i = (b * 256 + tid) * 2;
        int m = i >> 10, d = i & 1023;
        float v0 = a.hid[i], v1 = a.hid[i + 1];
        *(float2*)&a.h[i] = make_float2(v0, v1);
        __nv_bfloat162 hv, lv;
        split2(v0, hv.x, lv.x); split2(v1, hv.y, lv.y);
        const size_t off = pa_off(m >> 6, d >> 6, m & 63, (d & 63) * 2);
        *(__nv_bfloat162*)(a.hP + off) = hv;
        *(__nv_bfloat162*)(a.hP + off + 8192) = lv;
    }
}

__global__ void copyf_kernel(const float* __restrict__ s, float* __restrict__ d, int n)
{
    int i = blockIdx.x * 256 + threadIdx.x;
    if (i < n) d[i] = s[i];
}

// ---------------------------------------------------------------------------
extern "C" void kernel_launch(void* const* d_in, const int* in_sizes, int n_in,
                              void* d_out, int out_size)
{
    const float* enc = (const float*)d_in[0];
    const float* hid = (const float*)d_in[1];
    const float* Wa  = (const float*)d_in[3];
    const float* ba  = (const float*)d_in[4];
    const float* Wc  = (const float*)d_in[5];
    const float* bc  = (const float*)d_in[6];
    const float* Wih = (const float*)d_in[7];
    const float* Whh = (const float*)d_in[8];
    const float* bih = (const float*)d_in[9];
    const float* bhh = (const float*)d_in[10];
    const float* Wo  = (const float*)d_in[11];
    const float* bo  = (const float*)d_in[12];

    float* outseq = (float*)d_out;
    float* outh   = outseq + (size_t)BB * TT * HH;

    __nv_bfloat16 *pWoT_hi, *pWoT_lo, *pWc1_hi, *pWc1_lo, *pWcF_hi, *pWcF_lo;
    char *pWihP, *pWhhUP, *pWoP, *pWcBP, *pencP, *pgrP, *phP, *pHallP;
    float *ph, *pgi, *pghU, *pzero, *pWaF, *pbaF, *pbiasG, *pencW, *pP;
    cudaGetSymbolAddress((void**)&pWoT_hi, g_WoT_hi); cudaGetSymbolAddress((void**)&pWoT_lo, g_WoT_lo);
    cudaGetSymbolAddress((void**)&pWc1_hi, g_Wc1_hi); cudaGetSymbolAddress((void**)&pWc1_lo, g_Wc1_lo);
    cudaGetSymbolAddress((void**)&pWcF_hi, g_WcF_hi); cudaGetSymbolAddress((void**)&pWcF_lo, g_WcF_lo);
    cudaGetSymbolAddress((void**)&pWihP, g_WihP);     cudaGetSymbolAddress((void**)&pWhhUP, g_WhhUP);
    cudaGetSymbolAddress((void**)&pWoP, g_WoP);       cudaGetSymbolAddress((void**)&pWcBP, g_WcBP);
    cudaGetSymbolAddress((void**)&pencP, g_encP);     cudaGetSymbolAddress((void**)&pgrP, g_grP);
    cudaGetSymbolAddress((void**)&phP, g_hP);         cudaGetSymbolAddress((void**)&pHallP, g_HallP);
    cudaGetSymbolAddress((void**)&ph, g_h);           cudaGetSymbolAddress((void**)&pgi, g_gi);
    cudaGetSymbolAddress((void**)&pghU, g_ghU);       cudaGetSymbolAddress((void**)&pzero, g_zero);
    cudaGetSymbolAddress((void**)&pWaF, g_WaF);       cudaGetSymbolAddress((void**)&pbaF, g_baF);
    cudaGetSymbolAddress((void**)&pbiasG, g_biasGhU);
    cudaGetSymbolAddress((void**)&pencW, g_encW);     cudaGetSymbolAddress((void**)&pP, g_P);

    cudaFuncSetAttribute(gemm_std_kernel, cudaFuncAttributeMaxDynamicSharedMemorySize, ENG_SMEM);
    cudaFuncSetAttribute(gemm4_kernel, cudaFuncAttributeMaxDynamicSharedMemorySize, V4_SMEM);
    cudaFuncSetAttribute(stepA_kernel, cudaFuncAttributeMaxDynamicSharedMemorySize, V4_SMEM);
    cudaFuncSetAttribute(stepB_kernel, cudaFuncAttributeMaxDynamicSharedMemorySize, V4_SMEM);

    // ---- launch 1: mega setup (all splits/packs/folds) ----
    {
        SetupArgs s{};
        s.Wih = Wih; s.Whh = Whh; s.Wo = Wo; s.Wc = Wc; s.enc = enc;
        s.Wa = Wa; s.ba = ba; s.bo = bo; s.bc = bc; s.bhh = bhh; s.hid = hid;
        s.WihP = pWihP; s.WhhUP = pWhhUP; s.WoP = pWoP; s.WcBP = pWcBP;
        s.encP = pencP; s.hP = phP;
        s.WoT_hi = pWoT_hi; s.WoT_lo = pWoT_lo; s.Wc1_hi = pWc1_hi; s.Wc1_lo = pWc1_lo;
        s.WaF = pWaF; s.baF = pbaF; s.biasG = pbiasG; s.h = ph;
        mega_setup_kernel<<<MS_TOTAL, 256>>>(s);
    }
    // ---- launch 2: encW = enc @ WcB^T (v4 engine, M=32768) ----
    gemm4_kernel<<<dim3(8, 512), 256, V4_SMEM>>>(pencP, pWcBP, pzero, pencW, 1024, 1, 0);
    // ---- launch 3: WcF = Wc1 @ Wo (v3, split bf16 out) ----
    {
        GProb p = { pWc1_hi, pWc1_lo, 1024, pWoT_hi, pWoT_lo, 1024, 1024,
                    pzero, nullptr, 0, pWcF_hi, pWcF_lo, 1024, 2 };
        gemm_std_kernel<<<dim3(8, 16), 256, ENG_SMEM>>>(p);
    }
    // ---- launches 4+5: pack WcF into WhhUP rows [3072, 4096) ----
    pack_w_kernel<<<1024, 256>>>(pWcF_hi, pWcF_lo, 512, pWhhUP, 3072);
    pack_w_kernel<<<1024, 256>>>(pWcF_hi + 512 * 1024, pWcF_lo + 512 * 1024, 512, pWhhUP, 3584);

    // ---- decode loop (launch #6 = stepA t=0 -> ncu capture target) ----
    for (int t = 0; t < TT; ++t) {
        {
            StepAArgs a{};
            a.hP = phP; a.WhhUP = pWhhUP; a.biasG = pbiasG; a.ghU = pghU;
            a.h = ph; a.encW = pencW;
            a.W = (t == 0) ? (Wa + 1024) : pWaF;
            a.wld = (t == 0) ? 2048 : 1024;
            a.bias = (t == 0) ? ba : pbaF;
            a.P = pP;
            stepA_kernel<<<768, 256, V4_SMEM>>>(a);
        }
        gruin_kernel<<<BB * HH / 512, 256>>>(pP, pghU, bc, t, pgrP);
        {
            StepBArgs a{};
            a.grP = pgrP; a.WihP = pWihP; a.bih = bih; a.gi = pgi;
            a.HallP = pHallP; a.WoP = pWoP; a.bo = bo; a.outseq = outseq;
            a.t = t;
            stepB_kernel<<<(t >= 64) ? 256 : 192, 256, V4_SMEM>>>(a);
        }
        gate_kernel<<<BB * HH / 512, 256>>>(pgi, pghU, ph, phP, pHallP, t);
    }

    // ---- tail: odd Hall mtiles of outseq = Hall @ Wo^T + bo ----
    gemm4_kernel<<<dim3(8, 512), 256, V4_SMEM>>>(pHallP, pWoP, bo, outseq, 1024, 2, 1);

    if (out_size >= BB * TT * HH + BB * HH) {
        copyf_kernel<<<BB * HH / 256, 256>>>(ph, outh, BB * HH);
    }
}